// round 3
// baseline (speedup 1.0000x reference)
#include <cuda_runtime.h>
#include <math.h>

// Problem constants
#define B_      32
#define T_      64
#define V_      30000
#define E_      64
#define H_      64
#define O_      7
#define M_      2048            // B*T rows of the embed GEMM
#define KSPLIT  37              // 32 row-tiles * 37 = 1184 = 148 SMs * 8
#define KCHUNK  812             // even (float2-aligned); 37*812 = 30044 >= 30000
#define BK      40

// ---------------------------------------------------------------------------
// Scratch (device globals; no allocations allowed)
// ---------------------------------------------------------------------------
__device__ float g_partial[KSPLIT * M_ * E_];   // split-K partial GEMM outputs
__device__ float g_rowsum[KSPLIT * M_];         // split-K partial row sums of x
__device__ float g_embed[M_ * E_];              // relu((x@W)/rowsum)
__device__ float g_proj[3 * M_ * E_];           // [r,z,n] input projections + biases

// ---------------------------------------------------------------------------
// Packed fp32x2 FMA (Blackwell FFMA2 — 2x fp32 FMA throughput vs scalar FFMA)
// ---------------------------------------------------------------------------
__device__ __forceinline__ void ffma2(unsigned long long &c,
                                      unsigned long long a,
                                      unsigned long long b) {
    asm("fma.rn.f32x2 %0, %1, %2, %0;" : "+l"(c) : "l"(a), "l"(b));
}

// ---------------------------------------------------------------------------
// Kernel 1: split-K embed GEMM  out[row][e] += x[row][k] * W[k][e]
//   BM=64, BN=64(all of E), BK=40, 256 threads, 4x4 micro-tile via f32x2.
//   x tile stored DUPLICATED as (v,v) float2 pairs so the a-operand of the
//   packed FMA needs no pack-mov in the inner loop.
//   Also accumulates partial row sums of x (for the 1/sum(x) normalization).
// ---------------------------------------------------------------------------
__global__ void __launch_bounds__(256) k_embed_gemm(const float* __restrict__ x,
                                                    const float* __restrict__ w)
{
    __shared__ float2 xs2[BK * 66];   // xs2[kk*66 + m] = (x, x) duplicated
    __shared__ float  ws[BK * 64];    // ws[kk*64 + n]
    __shared__ float  rs_red[4 * 64];

    const int tid    = threadIdx.x;
    const int rt     = blockIdx.x;       // row tile
    const int s      = blockIdx.y;       // k split
    const int row0   = rt * 64;
    const int kstart = s * KCHUNK;
    const int kend   = min(kstart + KCHUNK, V_);
    const int tx     = tid & 15;         // col group: n0 = 4*tx
    const int ty     = tid >> 4;         // row group: m0 = 4*ty

    unsigned long long acc[4][2] = {};   // bits of (0.f,0.f)
    float rsum = 0.f;
    const int rs_row = tid & 63;
    const int rs_q   = tid >> 6;

    for (int kb = kstart; kb < kend; kb += BK) {
        // ---- load x tile: 64 rows x 40 k, transposed + duplicated ----
        #pragma unroll
        for (int i = 0; i < 5; i++) {
            int flat = tid + i * 256;            // 1280 float2 slots
            int r  = flat / 20;
            int c2 = flat % 20;
            int kg = kb + 2 * c2;                // even -> 8B aligned
            float2 v;
            if (kg + 2 <= kend) {
                v = *(const float2*)(x + (size_t)(row0 + r) * V_ + kg);
            } else {
                v.x = (kg < kend) ? x[(size_t)(row0 + r) * V_ + kg] : 0.f;
                v.y = 0.f;
            }
            xs2[(2 * c2) * 66 + r]     = make_float2(v.x, v.x);
            xs2[(2 * c2 + 1) * 66 + r] = make_float2(v.y, v.y);
        }
        // ---- load w tile: 40 rows x 64 ----
        #pragma unroll
        for (int i = 0; i < 5; i++) {
            int flat = tid + i * 256;            // 1280 float2
            int r  = flat >> 5;
            int c2 = flat & 31;
            int kg = kb + r;
            float2 v = make_float2(0.f, 0.f);
            if (kg < kend) v = *(const float2*)(w + (size_t)kg * 64 + 2 * c2);
            *(float2*)(ws + r * 64 + 2 * c2) = v;
        }
        __syncthreads();

        // ---- partial row sums (4 threads per row, 10 kk each) ----
        #pragma unroll
        for (int u = 0; u < 10; u++)
            rsum += xs2[(rs_q * 10 + u) * 66 + rs_row].x;

        // ---- main FFMA2 loop ----
        #pragma unroll
        for (int kk = 0; kk < BK; kk++) {
            const unsigned long long* xr =
                (const unsigned long long*)(xs2 + kk * 66 + 4 * ty);
            unsigned long long a0 = xr[0], a1 = xr[1], a2 = xr[2], a3 = xr[3];
            const unsigned long long* wr =
                (const unsigned long long*)(ws + kk * 64 + 4 * tx);
            unsigned long long w01 = wr[0], w23 = wr[1];
            ffma2(acc[0][0], a0, w01); ffma2(acc[0][1], a0, w23);
            ffma2(acc[1][0], a1, w01); ffma2(acc[1][1], a1, w23);
            ffma2(acc[2][0], a2, w01); ffma2(acc[2][1], a2, w23);
            ffma2(acc[3][0], a3, w01); ffma2(acc[3][1], a3, w23);
        }
        __syncthreads();
    }

    // ---- write partial tile ----
    #pragma unroll
    for (int i = 0; i < 4; i++) {
        size_t base = ((size_t)s * M_ + row0 + 4 * ty + i) * 64 + 4 * tx;
        *(float2*)(g_partial + base)     = *(float2*)&acc[i][0];
        *(float2*)(g_partial + base + 2) = *(float2*)&acc[i][1];
    }
    // ---- reduce the 4 per-row rowsum partials (deterministic, no atomics) --
    rs_red[rs_q * 64 + rs_row] = rsum;
    __syncthreads();
    if (tid < 64)
        g_rowsum[s * M_ + row0 + tid] =
            rs_red[tid] + rs_red[64 + tid] + rs_red[128 + tid] + rs_red[192 + tid];
}

// ---------------------------------------------------------------------------
// Kernel 2: reduce split-K partials -> embed = relu(dot / rowsum)
// ---------------------------------------------------------------------------
__global__ void k_reduce()
{
    int idx = blockIdx.x * 256 + threadIdx.x;   // grid 512 -> 131072 = M_*64
    int row = idx >> 6;
    float acc = 0.f, rs = 0.f;
    #pragma unroll
    for (int s = 0; s < KSPLIT; s++) acc += g_partial[(size_t)s * (M_ * 64) + idx];
    #pragma unroll
    for (int s = 0; s < KSPLIT; s++) rs += g_rowsum[s * M_ + row];
    g_embed[idx] = fmaxf(acc / rs, 0.f);
}

// ---------------------------------------------------------------------------
// Kernel 3: input projections  proj[m][row][j] = embed[row] . W_i*[j] + b_i*[j]
//   grid (32 row tiles, 3 matrices), 256 threads, 4x4 micro.
// ---------------------------------------------------------------------------
__global__ void __launch_bounds__(256) k_proj(const float* __restrict__ Wir,
                                              const float* __restrict__ Wiz,
                                              const float* __restrict__ Win,
                                              const float* __restrict__ bir,
                                              const float* __restrict__ biz,
                                              const float* __restrict__ bin)
{
    __shared__ float es[64 * 65];   // embed rows, padded
    __shared__ float wt[64 * 64];   // wt[e*64 + j] = W[j][e]
    const int tid = threadIdx.x;
    const int rt  = blockIdx.x;
    const int mat = blockIdx.y;
    const float* W  = (mat == 0) ? Wir : (mat == 1) ? Wiz : Win;
    const float* bb = (mat == 0) ? bir : (mat == 1) ? biz : bin;

    #pragma unroll
    for (int i = 0; i < 16; i++) {
        int flat = tid + i * 256;
        int r = flat >> 6, c = flat & 63;
        es[r * 65 + c] = g_embed[rt * 4096 + flat];
        wt[c * 64 + r] = W[flat];
    }
    __syncthreads();

    const int tx = tid & 15, ty = tid >> 4;
    float accf[4][4] = {};
    #pragma unroll
    for (int e = 0; e < 64; e++) {
        float a0 = es[(4 * ty + 0) * 65 + e];
        float a1 = es[(4 * ty + 1) * 65 + e];
        float a2 = es[(4 * ty + 2) * 65 + e];
        float a3 = es[(4 * ty + 3) * 65 + e];
        float w0 = wt[e * 64 + 4 * tx + 0];
        float w1 = wt[e * 64 + 4 * tx + 1];
        float w2 = wt[e * 64 + 4 * tx + 2];
        float w3 = wt[e * 64 + 4 * tx + 3];
        accf[0][0] = fmaf(a0, w0, accf[0][0]); accf[0][1] = fmaf(a0, w1, accf[0][1]);
        accf[0][2] = fmaf(a0, w2, accf[0][2]); accf[0][3] = fmaf(a0, w3, accf[0][3]);
        accf[1][0] = fmaf(a1, w0, accf[1][0]); accf[1][1] = fmaf(a1, w1, accf[1][1]);
        accf[1][2] = fmaf(a1, w2, accf[1][2]); accf[1][3] = fmaf(a1, w3, accf[1][3]);
        accf[2][0] = fmaf(a2, w0, accf[2][0]); accf[2][1] = fmaf(a2, w1, accf[2][1]);
        accf[2][2] = fmaf(a2, w2, accf[2][2]); accf[2][3] = fmaf(a2, w3, accf[2][3]);
        accf[3][0] = fmaf(a3, w0, accf[3][0]); accf[3][1] = fmaf(a3, w1, accf[3][1]);
        accf[3][2] = fmaf(a3, w2, accf[3][2]); accf[3][3] = fmaf(a3, w3, accf[3][3]);
    }
    float b0 = bb[4 * tx + 0], b1 = bb[4 * tx + 1];
    float b2 = bb[4 * tx + 2], b3 = bb[4 * tx + 3];
    #pragma unroll
    for (int i = 0; i < 4; i++) {
        int row = rt * 64 + 4 * ty + i;
        float* o = g_proj + (size_t)mat * (M_ * 64) + row * 64 + 4 * tx;
        o[0] = accf[i][0] + b0;
        o[1] = accf[i][1] + b1;
        o[2] = accf[i][2] + b2;
        o[3] = accf[i][3] + b3;
    }
}

// ---------------------------------------------------------------------------
// Kernel 4: per-batch GRU scan + output head. One block per batch element.
//   W_h* in smem, layout s[i*65 + j] = W[j][i] (conflict-free read & write).
//   Needs >48KB -> dynamic smem.
// ---------------------------------------------------------------------------
#define GRU_SMEM ((3 * 64 * 65 + 2 * 64) * 4)

__device__ __forceinline__ float sigm(float v) { return 1.f / (1.f + __expf(-v)); }

__global__ void __launch_bounds__(64) k_gru(const float* __restrict__ Whr,
                                            const float* __restrict__ Whz,
                                            const float* __restrict__ Whn,
                                            const float* __restrict__ bhr_g,
                                            const float* __restrict__ bhz_g,
                                            const float* __restrict__ bhn_g,
                                            const float* __restrict__ Wout,
                                            const float* __restrict__ bout,
                                            float* __restrict__ out)
{
    extern __shared__ float sm[];
    float* wr_s = sm;                  // [i*65 + j]
    float* wz_s = sm + 64 * 65;
    float* wn_s = sm + 2 * 64 * 65;
    float* ha   = sm + 3 * 64 * 65;    // ping
    float* hb   = ha + 64;             // pong

    const int j = threadIdx.x;
    const int b = blockIdx.x;

    // Load weights: coalesced global read, conflict-free smem write.
    #pragma unroll 8
    for (int k = 0; k < 64; k++) {
        int flat = k * 64 + j;         // W[k][j]
        wr_s[j * 65 + k] = Whr[flat];
        wz_s[j * 65 + k] = Whz[flat];
        wn_s[j * 65 + k] = Whn[flat];
    }
    const float bhr = bhr_g[j], bhz = bhz_g[j], bhn = bhn_g[j];

    const float* pr = g_proj;
    const float* pz = g_proj + M_ * 64;
    const float* pn = g_proj + 2 * M_ * 64;
    const int row0 = b * T_;

    // h0 from t=0 projections
    float z1 = sigm(pz[row0 * 64 + j]);
    float n1 = tanhf(pn[row0 * 64 + j]);
    ha[j] = (1.f - z1) * n1;
    __syncthreads();

    float* hc = ha;
    float* hx = hb;
    for (int t = 1; t < T_; t++) {
        int row = row0 + t;
        // prefetch input projections early (hide global latency behind dots)
        float xr = pr[row * 64 + j];
        float xz = pz[row * 64 + j];
        float xn = pn[row * 64 + j];
        float ar = bhr, az = bhz, an = bhn;
        #pragma unroll
        for (int i = 0; i < 64; i++) {
            float hv = hc[i];
            ar = fmaf(wr_s[i * 65 + j], hv, ar);
            az = fmaf(wz_s[i * 65 + j], hv, az);
            an = fmaf(wn_s[i * 65 + j], hv, an);
        }
        float r = sigm(xr + ar);
        float z = sigm(xz + az);
        float n = tanhf(xn + r * ar);
        hx[j] = (1.f - z) * n + z * hc[j];
        __syncthreads();
        float* tmp = hc; hc = hx; hx = tmp;
    }

    // output head: out[b][o] = h . W_out[o] + b_out[o]
    if (j < O_) {
        float acc = bout[j];
        #pragma unroll
        for (int k = 0; k < 64; k++) acc = fmaf(hc[k], Wout[j * 64 + k], acc);
        out[b * O_ + j] = acc;
    }
}

// ---------------------------------------------------------------------------
// Launch
// ---------------------------------------------------------------------------
extern "C" void kernel_launch(void* const* d_in, const int* in_sizes, int n_in,
                              void* d_out, int out_size)
{
    const float* x    = (const float*)d_in[0];
    const float* ve   = (const float*)d_in[1];
    const float* Wir  = (const float*)d_in[2];
    const float* Wiz  = (const float*)d_in[3];
    const float* Win  = (const float*)d_in[4];
    const float* Whr  = (const float*)d_in[5];
    const float* Whz  = (const float*)d_in[6];
    const float* Whn  = (const float*)d_in[7];
    const float* bir  = (const float*)d_in[8];
    const float* biz  = (const float*)d_in[9];
    const float* bin  = (const float*)d_in[10];
    const float* bhr  = (const float*)d_in[11];
    const float* bhz  = (const float*)d_in[12];
    const float* bhn  = (const float*)d_in[13];
    const float* Wout = (const float*)d_in[14];
    const float* bout = (const float*)d_in[15];
    (void)in_sizes; (void)n_in; (void)out_size;

    // >48KB dynamic smem opt-in (idempotent; not a stream op, capture-safe)
    cudaFuncSetAttribute(k_gru, cudaFuncAttributeMaxDynamicSharedMemorySize,
                         GRU_SMEM);

    k_embed_gemm<<<dim3(32, KSPLIT), 256>>>(x, ve);
    k_reduce<<<512, 256>>>();
    k_proj<<<dim3(32, 3), 256>>>(Wir, Wiz, Win, bir, biz, bin);
    k_gru<<<32, 64, GRU_SMEM>>>(Whr, Whz, Whn, bhr, bhz, bhn, Wout, bout,
                                (float*)d_out);
}

// round 4
// speedup vs baseline: 1.6309x; 1.6309x over previous
#include <cuda_runtime.h>
#include <math.h>

// Problem constants
#define B_      32
#define T_      64
#define V_      30000
#define E_      64
#define H_      64
#define O_      7
#define M_      2048            // B*T rows of the embed GEMM
#define KSPLIT  37              // 8 row-tiles * 37 = 296 = 148 SMs * 2
#define KCHUNK  812             // even; 37*812 = 30044 >= 30000
#define BM      256
#define BK      28

// ---------------------------------------------------------------------------
// Scratch (device globals; no allocations allowed)
// ---------------------------------------------------------------------------
__device__ float g_partial[KSPLIT * M_ * E_];   // [s][row][n]
__device__ float g_rowsum[KSPLIT * M_];
__device__ float g_embed[M_ * E_];
__device__ float g_proj[3 * M_ * E_];

typedef unsigned long long ull;

__device__ __forceinline__ void ffma2(ull &c, ull a, ull b) {
    asm("fma.rn.f32x2 %0, %1, %2, %0;" : "+l"(c) : "l"(a), "l"(b));
}
__device__ __forceinline__ ull dup2(float v) {
    ull d;
    asm("mov.b64 %0, {%1, %1};" : "=l"(d) : "f"(v));
    return d;
}

// ---------------------------------------------------------------------------
// Kernel 1: split-K embed GEMM, FFMA2-issue-balanced.
//   BM=256 rows, BN=64 (all of E), BK=28, 128 threads.
//   Micro-tile per thread: 8 rows x 16 cols (cols as 8 natural fp32 pairs).
//   x tile in smem NATURAL (transposed); a duplicated per-register via mov.b64.
//   w tile in smem as natural float2 pairs.
//   Per thread-kk: 96B crossbar / 128 lane-FMA  -> FFMA2-bound, not LDS-bound.
// ---------------------------------------------------------------------------
__global__ void __launch_bounds__(128, 2) k_embed_gemm(const float* __restrict__ x,
                                                       const float* __restrict__ w)
{
    __shared__ float  xs[BK * 260];    // xs[kk*260 + m], m<256, pad 4
    __shared__ float2 ws2[BK * 66];    // ws2[kk*66 + cp] = (w[k][2cp], w[k][2cp+1])

    const int tid    = threadIdx.x;
    const int rt     = blockIdx.x;       // row tile (8)
    const int s      = blockIdx.y;       // k split (37)
    const int row0   = rt * BM;
    const int kstart = s * KCHUNK;
    const int kend   = min(kstart + KCHUNK, V_);
    const int tx     = tid & 3;          // col group: cols 16*tx .. +16
    const int ty     = tid >> 2;         // row group: rows 8*ty .. +8

    ull acc[8][8];                       // [row r][colpair cp]
    #pragma unroll
    for (int r = 0; r < 8; r++)
        #pragma unroll
        for (int c = 0; c < 8; c++) acc[r][c] = 0ull;

    float rsum0 = 0.f, rsum1 = 0.f;      // rows 2*tid, 2*tid+1

    for (int kb = kstart; kb < kend; kb += BK) {
        // ---- load x tile: 256 rows x 28 k (float2 along k), store transposed
        #pragma unroll
        for (int i = 0; i < 28; i++) {
            int flat = tid + i * 128;          // 3584 float2 slots
            int r  = flat / 14;
            int p  = flat % 14;
            int kg = kb + 2 * p;               // even -> aligned; kend even ->
            float2 v = make_float2(0.f, 0.f);  // pairs never straddle kend
            if (kg < kend)
                v = *(const float2*)(x + (size_t)(row0 + r) * V_ + kg);
            xs[(2 * p) * 260 + r]     = v.x;
            xs[(2 * p + 1) * 260 + r] = v.y;
        }
        // ---- load w tile: 28 k-rows x 64 cols as natural float2 pairs ----
        #pragma unroll
        for (int i = 0; i < 7; i++) {
            int flat = tid + i * 128;          // 896 float2
            int kk = flat >> 5;
            int cp = flat & 31;
            int kg = kb + kk;
            float2 v = make_float2(0.f, 0.f);
            if (kg < kend) v = *(const float2*)(w + (size_t)kg * 64 + 2 * cp);
            ws2[kk * 66 + cp] = v;
        }
        __syncthreads();

        // ---- partial row sums (thread owns rows 2*tid, 2*tid+1) ----
        #pragma unroll
        for (int kk = 0; kk < BK; kk++) {
            float2 v = *(const float2*)(xs + kk * 260 + 2 * tid);
            rsum0 += v.x; rsum1 += v.y;
        }

        // ---- main FFMA2 loop ----
        #pragma unroll
        for (int kk = 0; kk < BK; kk++) {
            const float* xrow = xs + kk * 260 + 8 * ty;
            float4 a0 = *(const float4*)(xrow);
            float4 a1 = *(const float4*)(xrow + 4);
            ull A[8];
            A[0] = dup2(a0.x); A[1] = dup2(a0.y);
            A[2] = dup2(a0.z); A[3] = dup2(a0.w);
            A[4] = dup2(a1.x); A[5] = dup2(a1.y);
            A[6] = dup2(a1.z); A[7] = dup2(a1.w);
            const ull* wrow = (const ull*)(ws2 + kk * 66 + 8 * tx);
            ull W[8];
            #pragma unroll
            for (int c = 0; c < 8; c++) W[c] = wrow[c];
            #pragma unroll
            for (int r = 0; r < 8; r++)
                #pragma unroll
                for (int c = 0; c < 8; c++)
                    ffma2(acc[r][c], A[r], W[c]);
        }
        __syncthreads();
    }

    // ---- write partial tile (col-pairs contiguous in row-major [row][n]) --
    #pragma unroll
    for (int r = 0; r < 8; r++) {
        size_t base = ((size_t)s * M_ + row0 + 8 * ty + r) * 64 + 16 * tx;
        #pragma unroll
        for (int c = 0; c < 8; c++)
            *(float2*)(g_partial + base + 2 * c) = *(float2*)&acc[r][c];
    }
    // ---- row sums ----
    *(float2*)(g_rowsum + s * M_ + row0 + 2 * tid) = make_float2(rsum0, rsum1);
}

// ---------------------------------------------------------------------------
// Kernel 2: reduce split-K partials -> embed = relu(dot / rowsum)
// ---------------------------------------------------------------------------
__global__ void k_reduce()
{
    int idx = blockIdx.x * 256 + threadIdx.x;   // grid 512 -> 131072 = M_*64
    int row = idx >> 6;
    float acc = 0.f, rs = 0.f;
    #pragma unroll
    for (int s = 0; s < KSPLIT; s++) acc += g_partial[(size_t)s * (M_ * 64) + idx];
    #pragma unroll
    for (int s = 0; s < KSPLIT; s++) rs += g_rowsum[s * M_ + row];
    g_embed[idx] = fmaxf(acc / rs, 0.f);
}

// ---------------------------------------------------------------------------
// Kernel 3: input projections  proj[m][row][j] = embed[row] . W_i*[j] + b_i*[j]
// ---------------------------------------------------------------------------
__global__ void __launch_bounds__(256) k_proj(const float* __restrict__ Wir,
                                              const float* __restrict__ Wiz,
                                              const float* __restrict__ Win,
                                              const float* __restrict__ bir,
                                              const float* __restrict__ biz,
                                              const float* __restrict__ bin)
{
    __shared__ float es[64 * 65];
    __shared__ float wt[64 * 64];
    const int tid = threadIdx.x;
    const int rt  = blockIdx.x;
    const int mat = blockIdx.y;
    const float* W  = (mat == 0) ? Wir : (mat == 1) ? Wiz : Win;
    const float* bb = (mat == 0) ? bir : (mat == 1) ? biz : bin;

    #pragma unroll
    for (int i = 0; i < 16; i++) {
        int flat = tid + i * 256;
        int r = flat >> 6, c = flat & 63;
        es[r * 65 + c] = g_embed[rt * 4096 + flat];
        wt[c * 64 + r] = W[flat];
    }
    __syncthreads();

    const int tx = tid & 15, ty = tid >> 4;
    float accf[4][4] = {};
    #pragma unroll
    for (int e = 0; e < 64; e++) {
        float a0 = es[(4 * ty + 0) * 65 + e];
        float a1 = es[(4 * ty + 1) * 65 + e];
        float a2 = es[(4 * ty + 2) * 65 + e];
        float a3 = es[(4 * ty + 3) * 65 + e];
        float w0 = wt[e * 64 + 4 * tx + 0];
        float w1 = wt[e * 64 + 4 * tx + 1];
        float w2 = wt[e * 64 + 4 * tx + 2];
        float w3 = wt[e * 64 + 4 * tx + 3];
        accf[0][0] = fmaf(a0, w0, accf[0][0]); accf[0][1] = fmaf(a0, w1, accf[0][1]);
        accf[0][2] = fmaf(a0, w2, accf[0][2]); accf[0][3] = fmaf(a0, w3, accf[0][3]);
        accf[1][0] = fmaf(a1, w0, accf[1][0]); accf[1][1] = fmaf(a1, w1, accf[1][1]);
        accf[1][2] = fmaf(a1, w2, accf[1][2]); accf[1][3] = fmaf(a1, w3, accf[1][3]);
        accf[2][0] = fmaf(a2, w0, accf[2][0]); accf[2][1] = fmaf(a2, w1, accf[2][1]);
        accf[2][2] = fmaf(a2, w2, accf[2][2]); accf[2][3] = fmaf(a2, w3, accf[2][3]);
        accf[3][0] = fmaf(a3, w0, accf[3][0]); accf[3][1] = fmaf(a3, w1, accf[3][1]);
        accf[3][2] = fmaf(a3, w2, accf[3][2]); accf[3][3] = fmaf(a3, w3, accf[3][3]);
    }
    float b0 = bb[4 * tx + 0], b1 = bb[4 * tx + 1];
    float b2 = bb[4 * tx + 2], b3 = bb[4 * tx + 3];
    #pragma unroll
    for (int i = 0; i < 4; i++) {
        int row = rt * 64 + 4 * ty + i;
        float* o = g_proj + (size_t)mat * (M_ * 64) + row * 64 + 4 * tx;
        o[0] = accf[i][0] + b0;
        o[1] = accf[i][1] + b1;
        o[2] = accf[i][2] + b2;
        o[3] = accf[i][3] + b3;
    }
}

// ---------------------------------------------------------------------------
// Kernel 4: per-batch GRU scan + head. 256 threads/block, weights in REGS.
//   thread (j,q): j = tid>>2 owns output unit j, q = tid&3 owns 16-slice of
//   the 64-wide dot. 2-level shfl_xor reduction within lane quads.
// ---------------------------------------------------------------------------
__device__ __forceinline__ float sigm(float v) { return 1.f / (1.f + __expf(-v)); }

__global__ void __launch_bounds__(256) k_gru(const float* __restrict__ Whr,
                                             const float* __restrict__ Whz,
                                             const float* __restrict__ Whn,
                                             const float* __restrict__ bhr_g,
                                             const float* __restrict__ bhz_g,
                                             const float* __restrict__ bhn_g,
                                             const float* __restrict__ Wout,
                                             const float* __restrict__ bout,
                                             float* __restrict__ out)
{
    __shared__ float h0s[64];
    __shared__ float h1s[64];

    const int tid = threadIdx.x;
    const int j   = tid >> 2;
    const int q   = tid & 3;
    const int b   = blockIdx.x;

    // Weights rows j, columns 16q..16q+16, in registers (48 floats/thread).
    float4 wr[4], wz[4], wn[4];
    {
        const float4* r4 = (const float4*)(Whr + j * 64 + q * 16);
        const float4* z4 = (const float4*)(Whz + j * 64 + q * 16);
        const float4* n4 = (const float4*)(Whn + j * 64 + q * 16);
        #pragma unroll
        for (int u = 0; u < 4; u++) { wr[u] = r4[u]; wz[u] = z4[u]; wn[u] = n4[u]; }
    }
    const float bhr = bhr_g[j], bhz = bhz_g[j], bhn = bhn_g[j];

    const float* pr = g_proj;
    const float* pz = g_proj + M_ * 64;
    const float* pn = g_proj + 2 * M_ * 64;
    const int row0 = b * T_;

    // h0 from t=0 projections
    {
        float z1 = sigm(pz[row0 * 64 + j]);
        float n1 = tanhf(pn[row0 * 64 + j]);
        if (q == 0) h0s[j] = (1.f - z1) * n1;
    }
    __syncthreads();

    float* hc = h0s;
    float* hx = h1s;
    for (int t = 1; t < T_; t++) {
        const int row = row0 + t;
        float xr = pr[row * 64 + j];
        float xz = pz[row * 64 + j];
        float xn = pn[row * 64 + j];

        const float4* h4 = (const float4*)(hc + q * 16);
        float ar = 0.f, az = 0.f, an = 0.f;
        #pragma unroll
        for (int u = 0; u < 4; u++) {
            float4 hv = h4[u];
            ar = fmaf(wr[u].x, hv.x, ar); az = fmaf(wz[u].x, hv.x, az); an = fmaf(wn[u].x, hv.x, an);
            ar = fmaf(wr[u].y, hv.y, ar); az = fmaf(wz[u].y, hv.y, az); an = fmaf(wn[u].y, hv.y, an);
            ar = fmaf(wr[u].z, hv.z, ar); az = fmaf(wz[u].z, hv.z, az); an = fmaf(wn[u].z, hv.z, an);
            ar = fmaf(wr[u].w, hv.w, ar); az = fmaf(wz[u].w, hv.w, az); an = fmaf(wn[u].w, hv.w, an);
        }
        ar += __shfl_xor_sync(0xffffffffu, ar, 1);
        az += __shfl_xor_sync(0xffffffffu, az, 1);
        an += __shfl_xor_sync(0xffffffffu, an, 1);
        ar += __shfl_xor_sync(0xffffffffu, ar, 2);
        az += __shfl_xor_sync(0xffffffffu, az, 2);
        an += __shfl_xor_sync(0xffffffffu, an, 2);
        ar += bhr; az += bhz; an += bhn;     // hr/hz/hn now complete

        float r = sigm(xr + ar);
        float z = sigm(xz + az);
        float n = tanhf(xn + r * ar);
        float hold = hc[j];
        float hnew = (1.f - z) * n + z * hold;
        if (q == 0) hx[j] = hnew;
        __syncthreads();
        float* tmp = hc; hc = hx; hx = tmp;
    }

    // output head
    if (tid < O_) {
        float acc = bout[tid];
        #pragma unroll
        for (int k = 0; k < 64; k++) acc = fmaf(hc[k], Wout[tid * 64 + k], acc);
        out[b * O_ + tid] = acc;
    }
}

// ---------------------------------------------------------------------------
// Launch
// ---------------------------------------------------------------------------
extern "C" void kernel_launch(void* const* d_in, const int* in_sizes, int n_in,
                              void* d_out, int out_size)
{
    const float* x    = (const float*)d_in[0];
    const float* ve   = (const float*)d_in[1];
    const float* Wir  = (const float*)d_in[2];
    const float* Wiz  = (const float*)d_in[3];
    const float* Win  = (const float*)d_in[4];
    const float* Whr  = (const float*)d_in[5];
    const float* Whz  = (const float*)d_in[6];
    const float* Whn  = (const float*)d_in[7];
    const float* bir  = (const float*)d_in[8];
    const float* biz  = (const float*)d_in[9];
    const float* bin  = (const float*)d_in[10];
    const float* bhr  = (const float*)d_in[11];
    const float* bhz  = (const float*)d_in[12];
    const float* bhn  = (const float*)d_in[13];
    const float* Wout = (const float*)d_in[14];
    const float* bout = (const float*)d_in[15];
    (void)in_sizes; (void)n_in; (void)out_size;

    k_embed_gemm<<<dim3(8, KSPLIT), 128>>>(x, ve);
    k_reduce<<<512, 256>>>();
    k_proj<<<dim3(32, 3), 256>>>(Wir, Wiz, Win, bir, biz, bin);
    k_gru<<<32, 256>>>(Whr, Whz, Whn, bhr, bhz, bhn, Wout, bout,
                       (float*)d_out);
}

// round 5
// speedup vs baseline: 3.0999x; 1.9007x over previous
#include <cuda_runtime.h>
#include <math.h>
#include <stdint.h>

// Problem constants
#define B_      32
#define T_      64
#define V_      30000
#define E_      64
#define H_      64
#define O_      7
#define M_      2048
#define KSPLIT  18
#define KCHUNK  1728            // 27 * 64
#define BK      64

// ---------------------------------------------------------------------------
// Scratch
// ---------------------------------------------------------------------------
__device__ float g_partial[KSPLIT * M_ * E_];   // [s][row][n]
__device__ float g_rowsum[KSPLIT * M_];
__device__ float g_embed[M_ * E_];
__device__ float g_proj[3 * M_ * E_];

// ---------------------------------------------------------------------------
// MMA helpers (warp-level HMMA bf16, fp32 accum)
// ---------------------------------------------------------------------------
__device__ __forceinline__ void ldsm_x4(uint32_t* r, uint32_t addr) {
    asm volatile("ldmatrix.sync.aligned.m8n8.x4.shared.b16 {%0,%1,%2,%3}, [%4];"
        : "=r"(r[0]), "=r"(r[1]), "=r"(r[2]), "=r"(r[3]) : "r"(addr));
}
__device__ __forceinline__ void ldsm_x4_t(uint32_t* r, uint32_t addr) {
    asm volatile("ldmatrix.sync.aligned.m8n8.x4.trans.shared.b16 {%0,%1,%2,%3}, [%4];"
        : "=r"(r[0]), "=r"(r[1]), "=r"(r[2]), "=r"(r[3]) : "r"(addr));
}
__device__ __forceinline__ void mma_bf16(float* d, const uint32_t* a,
                                         uint32_t b0, uint32_t b1) {
    asm volatile("mma.sync.aligned.m16n8k16.row.col.f32.bf16.bf16.f32 "
        "{%0,%1,%2,%3}, {%4,%5,%6,%7}, {%8,%9}, {%0,%1,%2,%3};"
        : "+f"(d[0]), "+f"(d[1]), "+f"(d[2]), "+f"(d[3])
        : "r"(a[0]), "r"(a[1]), "r"(a[2]), "r"(a[3]), "r"(b0), "r"(b1));
}
// pack hi bf16 (truncated top-16) of two fp32 into one word (low = first)
__device__ __forceinline__ uint32_t pack_hi(uint32_t ax, uint32_t ay) {
    return __byte_perm(ax, ay, 0x7632);
}
// pack rounded bf16 of two fp32 (lo parts) -> word, low = first arg
__device__ __forceinline__ uint32_t pack_lo(float lx, float ly) {
    uint32_t w;
    asm("cvt.rn.bf16x2.f32 %0, %1, %2;" : "=r"(w) : "f"(ly), "f"(lx));
    return w;
}

// smem layout offsets (bytes)
#define A_HI 0
#define A_LO 16384
#define B_HI 32768
#define B_LO 40960

// ---------------------------------------------------------------------------
// Kernel 1: split-K embed GEMM on tensor cores (bf16 hi/lo split, 3 products)
//   Block: 128 rows x 64 cols, BK=64. 8 warps = 4 (m) x 2 (n); warp 32x32.
// ---------------------------------------------------------------------------
__global__ void __launch_bounds__(256, 2) k_embed_gemm(const float* __restrict__ x,
                                                       const float* __restrict__ w)
{
    __shared__ __align__(128) unsigned char smem[49152];
    const uint32_t sbase = (uint32_t)__cvta_generic_to_shared(smem);

    const int tid = threadIdx.x;
    const int wid = tid >> 5;
    const int l   = tid & 31;
    const int wr  = wid >> 1;          // 0..3  -> rows 32*wr
    const int wc  = wid & 1;           // 0..1  -> cols 32*wc
    const int rt  = blockIdx.x;        // 16 row tiles
    const int s   = blockIdx.y;        // 18 k splits
    const int row0   = rt * 128;
    const int kstart = s * KCHUNK;

    float d[2][2][8];                  // [mtile][nregion][ntile*4 + i]
    #pragma unroll
    for (int a = 0; a < 2; a++)
        #pragma unroll
        for (int b = 0; b < 2; b++)
            #pragma unroll
            for (int c = 0; c < 8; c++) d[a][b][c] = 0.f;

    float rsum = 0.f;
    const int xr_row = tid >> 1;            // row this thread loads
    const int xr_c0  = (tid & 1) * 8;       // float4 col base (0 or 8)

    // precompute ldmatrix lane geometry
    const int ml = l >> 3;                  // matrix id 0..3
    const int a_sub  = (ml & 1) * 8 + (l & 7);     // A row-in-16tile
    const int a_coff = (ml >> 1) * 16;             // A k-byte sub-offset
    const int b_krow_sub = ((l >> 3) & 1) * 8 + (l & 7);  // B k row in 16
    const int b_noff = ((l >> 4) & 1) * 16;        // B n-byte sub-offset

    for (int kb = kstart; kb < kstart + KCHUNK; kb += BK) {
        // ---------- global loads (before sync: overlap prev compute) ----------
        float4 xv[8];
        {
            const float* xp = x + (size_t)(row0 + xr_row) * V_ + kb;
            #pragma unroll
            for (int i = 0; i < 8; i++) {
                int c4 = xr_c0 + i;
                bool v = (kb + 4 * c4) < V_;
                xv[i] = v ? *(const float4*)(xp + 4 * c4)
                          : make_float4(0.f, 0.f, 0.f, 0.f);
            }
        }
        float4 wv[4];
        int wkt[4], wc4[4];
        #pragma unroll
        for (int i = 0; i < 4; i++) {
            int f = tid + 256 * i;
            wkt[i] = f >> 4;
            wc4[i] = f & 15;
            int kg = kb + wkt[i];
            bool v = kg < V_;
            wv[i] = v ? *(const float4*)(w + (size_t)kg * 64 + 4 * wc4[i])
                      : make_float4(0.f, 0.f, 0.f, 0.f);
        }

        __syncthreads();   // prev compute done before overwriting smem

        // ---------- convert + store x tile ----------
        #pragma unroll
        for (int i = 0; i < 8; i++) {
            int c4 = xr_c0 + i;
            uint32_t off = xr_row * 128 + 8 * c4;
            uint32_t sw  = off ^ ((xr_row & 7) << 4);
            uint32_t ax = __float_as_uint(xv[i].x), ay = __float_as_uint(xv[i].y);
            uint32_t az = __float_as_uint(xv[i].z), aw = __float_as_uint(xv[i].w);
            uint32_t h0 = pack_hi(ax, ay), h1 = pack_hi(az, aw);
            float lx = xv[i].x - __uint_as_float(ax & 0xFFFF0000u);
            float ly = xv[i].y - __uint_as_float(ay & 0xFFFF0000u);
            float lz = xv[i].z - __uint_as_float(az & 0xFFFF0000u);
            float lw = xv[i].w - __uint_as_float(aw & 0xFFFF0000u);
            *(uint2*)(smem + A_HI + sw) = make_uint2(h0, h1);
            *(uint2*)(smem + A_LO + sw) = make_uint2(pack_lo(lx, ly), pack_lo(lz, lw));
            rsum += xv[i].x + xv[i].y + xv[i].z + xv[i].w;
        }
        // ---------- convert + store W tile ----------
        #pragma unroll
        for (int i = 0; i < 4; i++) {
            uint32_t off = wkt[i] * 128 + 8 * wc4[i];
            uint32_t sw  = off ^ ((wkt[i] & 7) << 4);
            uint32_t ax = __float_as_uint(wv[i].x), ay = __float_as_uint(wv[i].y);
            uint32_t az = __float_as_uint(wv[i].z), aw = __float_as_uint(wv[i].w);
            float lx = wv[i].x - __uint_as_float(ax & 0xFFFF0000u);
            float ly = wv[i].y - __uint_as_float(ay & 0xFFFF0000u);
            float lz = wv[i].z - __uint_as_float(az & 0xFFFF0000u);
            float lw = wv[i].w - __uint_as_float(aw & 0xFFFF0000u);
            *(uint2*)(smem + B_HI + sw) = make_uint2(pack_hi(ax, ay), pack_hi(az, aw));
            *(uint2*)(smem + B_LO + sw) = make_uint2(pack_lo(lx, ly), pack_lo(lz, lw));
        }
        __syncthreads();

        // ---------- compute: 4 k16 steps ----------
        #pragma unroll
        for (int kk = 0; kk < 4; kk++) {
            uint32_t ah[2][4], al[2][4], bh[2][4], bl[2][4];
            #pragma unroll
            for (int mt = 0; mt < 2; mt++) {
                int row = wr * 32 + mt * 16 + a_sub;
                uint32_t off = row * 128 + (uint32_t)(kk * 32 + a_coff);
                uint32_t sw  = (off ^ ((row & 7) << 4));
                ldsm_x4(ah[mt], sbase + A_HI + sw);
                ldsm_x4(al[mt], sbase + A_LO + sw);
            }
            #pragma unroll
            for (int nr = 0; nr < 2; nr++) {
                int krow = kk * 16 + b_krow_sub;
                uint32_t off = krow * 128 + (uint32_t)((wc * 32 + nr * 16) * 2 + b_noff);
                uint32_t sw  = (off ^ ((krow & 7) << 4));
                ldsm_x4_t(bh[nr], sbase + B_HI + sw);
                ldsm_x4_t(bl[nr], sbase + B_LO + sw);
            }
            #pragma unroll
            for (int mt = 0; mt < 2; mt++)
                #pragma unroll
                for (int nr = 0; nr < 2; nr++)
                    #pragma unroll
                    for (int nt = 0; nt < 2; nt++) {
                        float* dd = &d[mt][nr][nt * 4];
                        mma_bf16(dd, ah[mt], bh[nr][2 * nt], bh[nr][2 * nt + 1]);
                        mma_bf16(dd, ah[mt], bl[nr][2 * nt], bl[nr][2 * nt + 1]);
                        mma_bf16(dd, al[mt], bh[nr][2 * nt], bh[nr][2 * nt + 1]);
                    }
        }
    }

    // ---------- epilogue ----------
    #pragma unroll
    for (int mt = 0; mt < 2; mt++)
        #pragma unroll
        for (int nr = 0; nr < 2; nr++)
            #pragma unroll
            for (int nt = 0; nt < 2; nt++) {
                int row = row0 + wr * 32 + mt * 16 + (l >> 2);
                int col = wc * 32 + nr * 16 + nt * 8 + (l & 3) * 2;
                float* dd = &d[mt][nr][nt * 4];
                size_t base = ((size_t)s * M_ + row) * 64 + col;
                *(float2*)(g_partial + base)            = make_float2(dd[0], dd[1]);
                *(float2*)(g_partial + base + 8 * 64)   = make_float2(dd[2], dd[3]);
            }
    // rowsum: thread pair (even,odd) covered one row
    rsum += __shfl_xor_sync(0xffffffffu, rsum, 1);
    if ((tid & 1) == 0)
        g_rowsum[s * M_ + row0 + (tid >> 1)] = rsum;
}

// ---------------------------------------------------------------------------
// Kernel 2: reduce split-K partials -> embed = relu(dot / rowsum)
// ---------------------------------------------------------------------------
__global__ void k_reduce()
{
    int idx = blockIdx.x * 256 + threadIdx.x;
    int row = idx >> 6;
    float acc = 0.f, rs = 0.f;
    #pragma unroll
    for (int s = 0; s < KSPLIT; s++) acc += g_partial[(size_t)s * (M_ * 64) + idx];
    #pragma unroll
    for (int s = 0; s < KSPLIT; s++) rs += g_rowsum[s * M_ + row];
    g_embed[idx] = fmaxf(acc / rs, 0.f);
}

// ---------------------------------------------------------------------------
// Kernel 3: input projections
// ---------------------------------------------------------------------------
__global__ void __launch_bounds__(256) k_proj(const float* __restrict__ Wir,
                                              const float* __restrict__ Wiz,
                                              const float* __restrict__ Win,
                                              const float* __restrict__ bir,
                                              const float* __restrict__ biz,
                                              const float* __restrict__ bin)
{
    __shared__ float es[64 * 65];
    __shared__ float wt[64 * 64];
    const int tid = threadIdx.x;
    const int rt  = blockIdx.x;
    const int mat = blockIdx.y;
    const float* W  = (mat == 0) ? Wir : (mat == 1) ? Wiz : Win;
    const float* bb = (mat == 0) ? bir : (mat == 1) ? biz : bin;

    #pragma unroll
    for (int i = 0; i < 16; i++) {
        int flat = tid + i * 256;
        int r = flat >> 6, c = flat & 63;
        es[r * 65 + c] = g_embed[rt * 4096 + flat];
        wt[c * 64 + r] = W[flat];
    }
    __syncthreads();

    const int tx = tid & 15, ty = tid >> 4;
    float accf[4][4] = {};
    #pragma unroll
    for (int e = 0; e < 64; e++) {
        float a0 = es[(4 * ty + 0) * 65 + e];
        float a1 = es[(4 * ty + 1) * 65 + e];
        float a2 = es[(4 * ty + 2) * 65 + e];
        float a3 = es[(4 * ty + 3) * 65 + e];
        float w0 = wt[e * 64 + 4 * tx + 0];
        float w1 = wt[e * 64 + 4 * tx + 1];
        float w2 = wt[e * 64 + 4 * tx + 2];
        float w3 = wt[e * 64 + 4 * tx + 3];
        accf[0][0] = fmaf(a0, w0, accf[0][0]); accf[0][1] = fmaf(a0, w1, accf[0][1]);
        accf[0][2] = fmaf(a0, w2, accf[0][2]); accf[0][3] = fmaf(a0, w3, accf[0][3]);
        accf[1][0] = fmaf(a1, w0, accf[1][0]); accf[1][1] = fmaf(a1, w1, accf[1][1]);
        accf[1][2] = fmaf(a1, w2, accf[1][2]); accf[1][3] = fmaf(a1, w3, accf[1][3]);
        accf[2][0] = fmaf(a2, w0, accf[2][0]); accf[2][1] = fmaf(a2, w1, accf[2][1]);
        accf[2][2] = fmaf(a2, w2, accf[2][2]); accf[2][3] = fmaf(a2, w3, accf[2][3]);
        accf[3][0] = fmaf(a3, w0, accf[3][0]); accf[3][1] = fmaf(a3, w1, accf[3][1]);
        accf[3][2] = fmaf(a3, w2, accf[3][2]); accf[3][3] = fmaf(a3, w3, accf[3][3]);
    }
    float b0 = bb[4 * tx + 0], b1 = bb[4 * tx + 1];
    float b2 = bb[4 * tx + 2], b3 = bb[4 * tx + 3];
    #pragma unroll
    for (int i = 0; i < 4; i++) {
        int row = rt * 64 + 4 * ty + i;
        float* o = g_proj + (size_t)mat * (M_ * 64) + row * 64 + 4 * tx;
        o[0] = accf[i][0] + b0;
        o[1] = accf[i][1] + b1;
        o[2] = accf[i][2] + b2;
        o[3] = accf[i][3] + b3;
    }
}

// ---------------------------------------------------------------------------
// Kernel 4: per-batch GRU scan + head.
//   All 63*3*64 input projections staged in smem up-front (no global loads in
//   the recurrence). Weights in registers, quad-shfl reduction, 1 bar/step.
// ---------------------------------------------------------------------------
#define GRU_SMEM ((3 * 4096 + 128) * 4)

__device__ __forceinline__ float sigm(float v) {
    return __fdividef(1.f, 1.f + __expf(-v));
}
__device__ __forceinline__ float tanh_fast(float v) {
    float e = __expf(2.f * v);
    return __fdividef(e - 1.f, e + 1.f);
}

__global__ void __launch_bounds__(256) k_gru(const float* __restrict__ Whr,
                                             const float* __restrict__ Whz,
                                             const float* __restrict__ Whn,
                                             const float* __restrict__ bhr_g,
                                             const float* __restrict__ bhz_g,
                                             const float* __restrict__ bhn_g,
                                             const float* __restrict__ Wout,
                                             const float* __restrict__ bout,
                                             float* __restrict__ out)
{
    extern __shared__ float sp[];
    float* sr = sp;                 // [t*64 + j]
    float* sz = sp + 4096;
    float* sn = sp + 8192;
    float* ha = sp + 12288;
    float* hb = ha + 64;

    const int tid = threadIdx.x;
    const int j   = tid >> 2;
    const int q   = tid & 3;
    const int b   = blockIdx.x;

    // stage all projections for this batch (coalesced float4 copies)
    #pragma unroll
    for (int m = 0; m < 3; m++) {
        const float4* src = (const float4*)(g_proj + (size_t)m * (M_ * 64) + b * 4096);
        float4* dst = (float4*)(sp + m * 4096);
        #pragma unroll
        for (int i = 0; i < 4; i++) {
            int idx = tid + i * 256;
            dst[idx] = src[idx];
        }
    }

    // weights rows j, cols 16q..16q+16 in registers
    float4 wr[4], wz[4], wn[4];
    {
        const float4* r4 = (const float4*)(Whr + j * 64 + q * 16);
        const float4* z4 = (const float4*)(Whz + j * 64 + q * 16);
        const float4* n4 = (const float4*)(Whn + j * 64 + q * 16);
        #pragma unroll
        for (int u = 0; u < 4; u++) { wr[u] = r4[u]; wz[u] = z4[u]; wn[u] = n4[u]; }
    }
    const float bhr = bhr_g[j], bhz = bhz_g[j], bhn = bhn_g[j];
    __syncthreads();

    // h0 from t=0 projections
    {
        float z1 = sigm(sz[j]);
        float n1 = tanh_fast(sn[j]);
        if (q == 0) ha[j] = (1.f - z1) * n1;
    }
    __syncthreads();

    float* hc = ha;
    float* hx = hb;
    for (int t = 1; t < T_; t++) {
        float xr = sr[t * 64 + j];
        float xz = sz[t * 64 + j];
        float xn = sn[t * 64 + j];

        const float4* h4 = (const float4*)(hc + q * 16);
        float4 hv0 = h4[0], hv1 = h4[1], hv2 = h4[2], hv3 = h4[3];

        // two accumulator chains per gate
        float ar0 = 0.f, az0 = 0.f, an0 = 0.f;
        float ar1 = 0.f, az1 = 0.f, an1 = 0.f;
        ar0 = fmaf(wr[0].x, hv0.x, ar0); az0 = fmaf(wz[0].x, hv0.x, az0); an0 = fmaf(wn[0].x, hv0.x, an0);
        ar0 = fmaf(wr[0].y, hv0.y, ar0); az0 = fmaf(wz[0].y, hv0.y, az0); an0 = fmaf(wn[0].y, hv0.y, an0);
        ar0 = fmaf(wr[0].z, hv0.z, ar0); az0 = fmaf(wz[0].z, hv0.z, az0); an0 = fmaf(wn[0].z, hv0.z, an0);
        ar0 = fmaf(wr[0].w, hv0.w, ar0); az0 = fmaf(wz[0].w, hv0.w, az0); an0 = fmaf(wn[0].w, hv0.w, an0);
        ar1 = fmaf(wr[1].x, hv1.x, ar1); az1 = fmaf(wz[1].x, hv1.x, az1); an1 = fmaf(wn[1].x, hv1.x, an1);
        ar1 = fmaf(wr[1].y, hv1.y, ar1); az1 = fmaf(wz[1].y, hv1.y, az1); an1 = fmaf(wn[1].y, hv1.y, an1);
        ar1 = fmaf(wr[1].z, hv1.z, ar1); az1 = fmaf(wz[1].z, hv1.z, az1); an1 = fmaf(wn[1].z, hv1.z, an1);
        ar1 = fmaf(wr[1].w, hv1.w, ar1); az1 = fmaf(wz[1].w, hv1.w, az1); an1 = fmaf(wn[1].w, hv1.w, an1);
        ar0 = fmaf(wr[2].x, hv2.x, ar0); az0 = fmaf(wz[2].x, hv2.x, az0); an0 = fmaf(wn[2].x, hv2.x, an0);
        ar0 = fmaf(wr[2].y, hv2.y, ar0); az0 = fmaf(wz[2].y, hv2.y, az0); an0 = fmaf(wn[2].y, hv2.y, an0);
        ar0 = fmaf(wr[2].z, hv2.z, ar0); az0 = fmaf(wz[2].z, hv2.z, az0); an0 = fmaf(wn[2].z, hv2.z, an0);
        ar0 = fmaf(wr[2].w, hv2.w, ar0); az0 = fmaf(wz[2].w, hv2.w, az0); an0 = fmaf(wn[2].w, hv2.w, an0);
        ar1 = fmaf(wr[3].x, hv3.x, ar1); az1 = fmaf(wz[3].x, hv3.x, az1); an1 = fmaf(wn[3].x, hv3.x, an1);
        ar1 = fmaf(wr[3].y, hv3.y, ar1); az1 = fmaf(wz[3].y, hv3.y, az1); an1 = fmaf(wn[3].y, hv3.y, an1);
        ar1 = fmaf(wr[3].z, hv3.z, ar1); az1 = fmaf(wz[3].z, hv3.z, az1); an1 = fmaf(wn[3].z, hv3.z, an1);
        ar1 = fmaf(wr[3].w, hv3.w, ar1); az1 = fmaf(wz[3].w, hv3.w, az1); an1 = fmaf(wn[3].w, hv3.w, an1);
        float ar = ar0 + ar1, az = az0 + az1, an = an0 + an1;

        ar += __shfl_xor_sync(0xffffffffu, ar, 1);
        az += __shfl_xor_sync(0xffffffffu, az, 1);
        an += __shfl_xor_sync(0xffffffffu, an, 1);
        ar += __shfl_xor_sync(0xffffffffu, ar, 2);
        az += __shfl_xor_sync(0xffffffffu, az, 2);
        an += __shfl_xor_sync(0xffffffffu, an, 2);
        ar += bhr; az += bhz; an += bhn;

        float r = sigm(xr + ar);
        float z = sigm(xz + az);
        float n = tanh_fast(xn + r * ar);
        float hold = hc[j];
        float hnew = (1.f - z) * n + z * hold;
        if (q == 0) hx[j] = hnew;
        __syncthreads();
        float* tmp = hc; hc = hx; hx = tmp;
    }

    if (tid < O_) {
        float acc = bout[tid];
        #pragma unroll
        for (int k = 0; k < 64; k++) acc = fmaf(hc[k], Wout[tid * 64 + k], acc);
        out[b * O_ + tid] = acc;
    }
}

// ---------------------------------------------------------------------------
// Launch
// ---------------------------------------------------------------------------
extern "C" void kernel_launch(void* const* d_in, const int* in_sizes, int n_in,
                              void* d_out, int out_size)
{
    const float* x    = (const float*)d_in[0];
    const float* ve   = (const float*)d_in[1];
    const float* Wir  = (const float*)d_in[2];
    const float* Wiz  = (const float*)d_in[3];
    const float* Win  = (const float*)d_in[4];
    const float* Whr  = (const float*)d_in[5];
    const float* Whz  = (const float*)d_in[6];
    const float* Whn  = (const float*)d_in[7];
    const float* bir  = (const float*)d_in[8];
    const float* biz  = (const float*)d_in[9];
    const float* bin  = (const float*)d_in[10];
    const float* bhr  = (const float*)d_in[11];
    const float* bhz  = (const float*)d_in[12];
    const float* bhn  = (const float*)d_in[13];
    const float* Wout = (const float*)d_in[14];
    const float* bout = (const float*)d_in[15];
    (void)in_sizes; (void)n_in; (void)out_size;

    cudaFuncSetAttribute(k_gru, cudaFuncAttributeMaxDynamicSharedMemorySize,
                         GRU_SMEM);

    k_embed_gemm<<<dim3(16, KSPLIT), 256>>>(x, ve);
    k_reduce<<<512, 256>>>();
    k_proj<<<dim3(32, 3), 256>>>(Wir, Wiz, Win, bir, biz, bin);
    k_gru<<<32, 256, GRU_SMEM>>>(Whr, Whz, Whn, bhr, bhz, bhn, Wout, bout,
                                 (float*)d_out);
}

// round 11
// speedup vs baseline: 3.6871x; 1.1894x over previous
#include <cuda_runtime.h>
#include <cuda_fp16.h>
#include <math.h>
#include <stdint.h>

// Problem constants
#define B_      32
#define T_      64
#define V_      30000
#define E_      64
#define H_      64
#define O_      7
#define M_      2048
#define KSPLIT  18
#define KCHUNK  1728            // 27 * 64
#define BK      64
#define NTILES  486             // KSPLIT * 27 (covers ceil(30000/64)=469, rest zero)

// ---------------------------------------------------------------------------
// Scratch (device globals; no allocations allowed)
// ---------------------------------------------------------------------------
__device__ float g_partial[KSPLIT * M_ * E_];   // [s][row][n]
__device__ float g_rowsum[KSPLIT * M_];
__device__ float g_embed[M_ * E_];
__device__ float g_proj[3 * M_ * E_];
// Pre-split, pre-swizzled W tiles: [tile][512 x uint4] = 8KB per 64k x 64n tile
__device__ uint4 g_whi[NTILES * 512];
__device__ uint4 g_wlo[NTILES * 512];

// ---------------------------------------------------------------------------
// MMA helpers (warp-level HMMA fp16, fp32 accum)
// ---------------------------------------------------------------------------
__device__ __forceinline__ void ldsm_x4(uint32_t* r, uint32_t addr) {
    asm volatile("ldmatrix.sync.aligned.m8n8.x4.shared.b16 {%0,%1,%2,%3}, [%4];"
        : "=r"(r[0]), "=r"(r[1]), "=r"(r[2]), "=r"(r[3]) : "r"(addr));
}
__device__ __forceinline__ void ldsm_x4_t(uint32_t* r, uint32_t addr) {
    asm volatile("ldmatrix.sync.aligned.m8n8.x4.trans.shared.b16 {%0,%1,%2,%3}, [%4];"
        : "=r"(r[0]), "=r"(r[1]), "=r"(r[2]), "=r"(r[3]) : "r"(addr));
}
__device__ __forceinline__ void mma_f16(float* d, const uint32_t* a,
                                        uint32_t b0, uint32_t b1) {
    asm volatile("mma.sync.aligned.m16n8k16.row.col.f32.f16.f16.f32 "
        "{%0,%1,%2,%3}, {%4,%5,%6,%7}, {%8,%9}, {%0,%1,%2,%3};"
        : "+f"(d[0]), "+f"(d[1]), "+f"(d[2]), "+f"(d[3])
        : "r"(a[0]), "r"(a[1]), "r"(a[2]), "r"(a[3]), "r"(b0), "r"(b1));
}
// pack two fp32 -> fp16x2 word, low half = first arg
__device__ __forceinline__ uint32_t pack_f16(float lo, float hi) {
    uint32_t w;
    asm("cvt.rn.f16x2.f32 %0, %1, %2;" : "=r"(w) : "f"(hi), "f"(lo));
    return w;
}
__device__ __forceinline__ void cp_async16(uint32_t smem_dst, const void* gsrc) {
    asm volatile("cp.async.cg.shared.global [%0], [%1], 16;"
        :: "r"(smem_dst), "l"(gsrc) : "memory");
}

// ---------------------------------------------------------------------------
// Kernel 0: W split prep. W (V x 64 fp32) -> hi/lo fp16 tiles, SW128-swizzled,
//   ldsm-ready 8KB per 64k x 64n tile. One block per tile. Runs once per call
//   (deterministic), ~15MB traffic -> a few microseconds.
// ---------------------------------------------------------------------------
__global__ void __launch_bounds__(256) k_wsplit(const float* __restrict__ w)
{
    const int t   = blockIdx.x;
    const int tid = threadIdx.x;
    const int np  = tid & 31;      // n-pair index (cols 2np, 2np+1)
    const int rq  = tid >> 5;      // 0..7

    char* hib_base = (char*)g_whi + (size_t)t * 8192;
    char* lob_base = (char*)g_wlo + (size_t)t * 8192;

    #pragma unroll
    for (int i = 0; i < 8; i++) {
        int kr = i * 8 + rq;                 // 0..63
        int kg = t * 64 + kr;
        float2 v = make_float2(0.f, 0.f);
        if (kg < V_) v = *(const float2*)(w + (size_t)kg * 64 + 2 * np);
        __half h0 = __float2half_rn(v.x), h1 = __float2half_rn(v.y);
        float l0 = v.x - __half2float(h0);
        float l1 = v.y - __half2float(h1);
        __half g0 = __float2half_rn(l0), g1 = __float2half_rn(l1);
        uint32_t hib = (uint32_t)__half_as_ushort(h0) |
                       ((uint32_t)__half_as_ushort(h1) << 16);
        uint32_t lob = (uint32_t)__half_as_ushort(g0) |
                       ((uint32_t)__half_as_ushort(g1) << 16);
        uint32_t off = (uint32_t)(kr * 128 + np * 4);
        uint32_t sw  = off ^ ((kr & 7) << 4);
        *(uint32_t*)(hib_base + sw) = hib;
        *(uint32_t*)(lob_base + sw) = lob;
    }
}

// ---------------------------------------------------------------------------
// Kernel 1: split-K embed GEMM (HMMA fp16).
//   x single fp16 (in-kernel convert); W pre-split hi/lo via cp.async
//   (double-buffered). fp32 rowsum from x registers (fma pipe, overlaps MMA).
//   CTA: M=128 x N=64, BK=64; 8 warps, each m16 x n64. Grid 16x18 = 1 wave.
// ---------------------------------------------------------------------------
__global__ void __launch_bounds__(256, 2) k_embed_gemm(const float* __restrict__ x)
{
    __shared__ __align__(128) unsigned char sA[16384];        // 128r x 64k fp16
    __shared__ __align__(128) unsigned char sB[2][16384];     // per buf: hi 8KB | lo 8KB

    const uint32_t aBase  = (uint32_t)__cvta_generic_to_shared(sA);
    const uint32_t bBase0 = (uint32_t)__cvta_generic_to_shared(sB[0]);
    const uint32_t bBase1 = (uint32_t)__cvta_generic_to_shared(sB[1]);

    const int tid = threadIdx.x;
    const int wr  = tid >> 5;          // warp id -> rows wr*16..+16
    const int l   = tid & 31;
    const int rt  = blockIdx.x;        // 16 row tiles
    const int s   = blockIdx.y;        // 18 k splits
    const int row0  = rt * 128;
    const int tile0 = s * 27;

    // x-load mapping: row = tid>>1, 8 float4 groups starting at (tid&1)*8
    const int xrow = tid >> 1;
    const int xcg  = (tid & 1) * 8;

    // ldmatrix lane geometry
    const int ml = l >> 3;
    const int a_sub  = (ml & 1) * 8 + (l & 7);
    const int a_coff = (ml >> 1) * 16;
    const int b_krow_sub = ((l >> 3) & 1) * 8 + (l & 7);
    const int b_noff     = ((l >> 4) & 1) * 16;

    float d[8][4];
    #pragma unroll
    for (int g = 0; g < 8; g++)
        #pragma unroll
        for (int i = 0; i < 4; i++) d[g][i] = 0.f;
    float rsum = 0.f;

    // ---- prologue: W(0) via cp.async; x(0) into registers ----
    {
        const uint4* src_h = g_whi + (size_t)tile0 * 512;
        const uint4* src_l = g_wlo + (size_t)tile0 * 512;
        #pragma unroll
        for (int j = 0; j < 2; j++) {
            int idx = tid + 256 * j;
            cp_async16(bBase0 + idx * 16,        src_h + idx);
            cp_async16(bBase0 + 8192 + idx * 16, src_l + idx);
        }
        asm volatile("cp.async.commit_group;" ::: "memory");
    }
    float4 xv[8];
    {
        const float* xp = x + (size_t)(row0 + xrow) * V_ + tile0 * 64;
        #pragma unroll
        for (int i = 0; i < 8; i++) {
            int c = 4 * (xcg + i);
            xv[i] = (tile0 * 64 + c < V_) ? __ldcs((const float4*)(xp + c))
                                          : make_float4(0.f, 0.f, 0.f, 0.f);
        }
    }

    for (int it = 0; it < 27; it++) {
        const uint32_t bCur = (it & 1) ? bBase1 : bBase0;

        __syncthreads();   // prior iteration's mma done -> sA free

        // ---- store x tile as fp16 (A: [m][k] 128B rows, SW128) + fp32 rowsum --
        #pragma unroll
        for (int i = 0; i < 8; i++) {
            uint32_t off = (uint32_t)(xrow * 128 + 8 * (xcg + i));
            uint32_t sw  = off ^ ((xrow & 7) << 4);
            uint32_t w0 = pack_f16(xv[i].x, xv[i].y);
            uint32_t w1 = pack_f16(xv[i].z, xv[i].w);
            *(uint2*)(sA + sw) = make_uint2(w0, w1);
            rsum += (xv[i].x + xv[i].y) + (xv[i].z + xv[i].w);
        }

        // ---- prefetch W(it+1) into other buffer ----
        if (it < 26) {
            const uint32_t bNext = (it & 1) ? bBase0 : bBase1;
            const uint4* src_h = g_whi + (size_t)(tile0 + it + 1) * 512;
            const uint4* src_l = g_wlo + (size_t)(tile0 + it + 1) * 512;
            #pragma unroll
            for (int j = 0; j < 2; j++) {
                int idx = tid + 256 * j;
                cp_async16(bNext + idx * 16,        src_h + idx);
                cp_async16(bNext + 8192 + idx * 16, src_l + idx);
            }
            asm volatile("cp.async.commit_group;" ::: "memory");
            asm volatile("cp.async.wait_group 1;" ::: "memory");  // W(it) arrived
        } else {
            asm volatile("cp.async.wait_group 0;" ::: "memory");
        }
        __syncthreads();   // A + W(it) visible to all warps

        // ---- prefetch x(it+1) into regs (hidden behind mma below) ----
        if (it < 26) {
            int kb = (tile0 + it + 1) * 64;
            const float* xp = x + (size_t)(row0 + xrow) * V_ + kb;
            #pragma unroll
            for (int i = 0; i < 8; i++) {
                int c = 4 * (xcg + i);
                xv[i] = (kb + c < V_) ? __ldcs((const float4*)(xp + c))
                                      : make_float4(0.f, 0.f, 0.f, 0.f);
            }
        }

        // ---- mma: 4 k16 steps x (4 n16 regions x 2 products) ----
        #pragma unroll
        for (int kk = 0; kk < 4; kk++) {
            uint32_t a[4];
            {
                int row = wr * 16 + a_sub;
                uint32_t off = (uint32_t)(row * 128 + kk * 32 + a_coff);
                ldsm_x4(a, aBase + (off ^ ((row & 7) << 4)));
            }
            #pragma unroll
            for (int nr = 0; nr < 4; nr++) {
                int krow = kk * 16 + b_krow_sub;
                uint32_t off = (uint32_t)(krow * 128 + nr * 32 + b_noff);
                uint32_t sw  = off ^ ((krow & 7) << 4);
                uint32_t bh[4], bl[4];
                ldsm_x4_t(bh, bCur + sw);
                ldsm_x4_t(bl, bCur + 8192 + sw);
                mma_f16(d[nr * 2 + 0], a, bh[0], bh[1]);
                mma_f16(d[nr * 2 + 1], a, bh[2], bh[3]);
                mma_f16(d[nr * 2 + 0], a, bl[0], bl[1]);
                mma_f16(d[nr * 2 + 1], a, bl[2], bl[3]);
            }
        }
    }

    // ---- epilogue: write partial tile ----
    {
        int r0 = row0 + wr * 16 + (l >> 2);
        #pragma unroll
        for (int g = 0; g < 8; g++) {
            int col = g * 8 + (l & 3) * 2;
            size_t base = ((size_t)s * M_ + r0) * 64 + col;
            *(float2*)(g_partial + base)       = make_float2(d[g][0], d[g][1]);
            *(float2*)(g_partial + base + 512) = make_float2(d[g][2], d[g][3]);
        }
    }
    // ---- rowsum: thread pair (even,odd) covered one row ----
    rsum += __shfl_xor_sync(0xffffffffu, rsum, 1);
    if ((tid & 1) == 0)
        g_rowsum[s * M_ + row0 + xrow] = rsum;
}

// ---------------------------------------------------------------------------
// Kernel 2: reduce split-K partials -> embed = relu(dot / rowsum)
// ---------------------------------------------------------------------------
__global__ void k_reduce()
{
    int idx = blockIdx.x * 256 + threadIdx.x;
    int row = idx >> 6;
    float acc = 0.f, rs = 0.f;
    #pragma unroll
    for (int s = 0; s < KSPLIT; s++) acc += g_partial[(size_t)s * (M_ * 64) + idx];
    #pragma unroll
    for (int s = 0; s < KSPLIT; s++) rs += g_rowsum[s * M_ + row];
    g_embed[idx] = fmaxf(acc / rs, 0.f);
}

// ---------------------------------------------------------------------------
// Kernel 3: input projections
// ---------------------------------------------------------------------------
__global__ void __launch_bounds__(256) k_proj(const float* __restrict__ Wir,
                                              const float* __restrict__ Wiz,
                                              const float* __restrict__ Win,
                                              const float* __restrict__ bir,
                                              const float* __restrict__ biz,
                                              const float* __restrict__ bin)
{
    __shared__ float es[64 * 65];
    __shared__ float wt[64 * 64];
    const int tid = threadIdx.x;
    const int rt  = blockIdx.x;
    const int mat = blockIdx.y;
    const float* W  = (mat == 0) ? Wir : (mat == 1) ? Wiz : Win;
    const float* bb = (mat == 0) ? bir : (mat == 1) ? biz : bin;

    #pragma unroll
    for (int i = 0; i < 16; i++) {
        int flat = tid + i * 256;
        int r = flat >> 6, c = flat & 63;
        es[r * 65 + c] = g_embed[rt * 4096 + flat];
        wt[c * 64 + r] = W[flat];
    }
    __syncthreads();

    const int tx = tid & 15, ty = tid >> 4;
    float accf[4][4] = {};
    #pragma unroll
    for (int e = 0; e < 64; e++) {
        float a0 = es[(4 * ty + 0) * 65 + e];
        float a1 = es[(4 * ty + 1) * 65 + e];
        float a2 = es[(4 * ty + 2) * 65 + e];
        float a3 = es[(4 * ty + 3) * 65 + e];
        float w0 = wt[e * 64 + 4 * tx + 0];
        float w1 = wt[e * 64 + 4 * tx + 1];
        float w2 = wt[e * 64 + 4 * tx + 2];
        float w3 = wt[e * 64 + 4 * tx + 3];
        accf[0][0] = fmaf(a0, w0, accf[0][0]); accf[0][1] = fmaf(a0, w1, accf[0][1]);
        accf[0][2] = fmaf(a0, w2, accf[0][2]); accf[0][3] = fmaf(a0, w3, accf[0][3]);
        accf[1][0] = fmaf(a1, w0, accf[1][0]); accf[1][1] = fmaf(a1, w1, accf[1][1]);
        accf[1][2] = fmaf(a1, w2, accf[1][2]); accf[1][3] = fmaf(a1, w3, accf[1][3]);
        accf[2][0] = fmaf(a2, w0, accf[2][0]); accf[2][1] = fmaf(a2, w1, accf[2][1]);
        accf[2][2] = fmaf(a2, w2, accf[2][2]); accf[2][3] = fmaf(a2, w3, accf[2][3]);
        accf[3][0] = fmaf(a3, w0, accf[3][0]); accf[3][1] = fmaf(a3, w1, accf[3][1]);
        accf[3][2] = fmaf(a3, w2, accf[3][2]); accf[3][3] = fmaf(a3, w3, accf[3][3]);
    }
    float b0 = bb[4 * tx + 0], b1 = bb[4 * tx + 1];
    float b2 = bb[4 * tx + 2], b3 = bb[4 * tx + 3];
    #pragma unroll
    for (int i = 0; i < 4; i++) {
        int row = rt * 64 + 4 * ty + i;
        float* o = g_proj + (size_t)mat * (M_ * 64) + row * 64 + 4 * tx;
        o[0] = accf[i][0] + b0;
        o[1] = accf[i][1] + b1;
        o[2] = accf[i][2] + b2;
        o[3] = accf[i][3] + b3;
    }
}

// ---------------------------------------------------------------------------
// Kernel 4: per-batch GRU scan + head (proj staged in smem, weights in regs)
// ---------------------------------------------------------------------------
#define GRU_SMEM ((3 * 4096 + 128) * 4)

__device__ __forceinline__ float sigm(float v) {
    return __fdividef(1.f, 1.f + __expf(-v));
}
__device__ __forceinline__ float tanh_fast(float v) {
    float e = __expf(2.f * v);
    return __fdividef(e - 1.f, e + 1.f);
}

__global__ void __launch_bounds__(256) k_gru(const float* __restrict__ Whr,
                                             const float* __restrict__ Whz,
                                             const float* __restrict__ Whn,
                                             const float* __restrict__ bhr_g,
                                             const float* __restrict__ bhz_g,
                                             const float* __restrict__ bhn_g,
                                             const float* __restrict__ Wout,
                                             const float* __restrict__ bout,
                                             float* __restrict__ out)
{
    extern __shared__ float sp[];
    float* sr = sp;
    float* sz = sp + 4096;
    float* sn = sp + 8192;
    float* ha = sp + 12288;
    float* hb = ha + 64;

    const int tid = threadIdx.x;
    const int j   = tid >> 2;
    const int q   = tid & 3;
    const int b   = blockIdx.x;

    #pragma unroll
    for (int m = 0; m < 3; m++) {
        const float4* src = (const float4*)(g_proj + (size_t)m * (M_ * 64) + b * 4096);
        float4* dst = (float4*)(sp + m * 4096);
        #pragma unroll
        for (int i = 0; i < 4; i++) {
            int idx = tid + i * 256;
            dst[idx] = src[idx];
        }
    }

    float4 wr[4], wz[4], wn[4];
    {
        const float4* r4 = (const float4*)(Whr + j * 64 + q * 16);
        const float4* z4 = (const float4*)(Whz + j * 64 + q * 16);
        const float4* n4 = (const float4*)(Whn + j * 64 + q * 16);
        #pragma unroll
        for (int u = 0; u < 4; u++) { wr[u] = r4[u]; wz[u] = z4[u]; wn[u] = n4[u]; }
    }
    const float bhr = bhr_g[j], bhz = bhz_g[j], bhn = bhn_g[j];
    __syncthreads();

    {
        float z1 = sigm(sz[j]);
        float n1 = tanh_fast(sn[j]);
        if (q == 0) ha[j] = (1.f - z1) * n1;
    }
    __syncthreads();

    float* hc = ha;
    float* hx = hb;
    for (int t = 1; t < T_; t++) {
        float xr = sr[t * 64 + j];
        float xz = sz[t * 64 + j];
        float xn = sn[t * 64 + j];

        const float4* h4 = (const float4*)(hc + q * 16);
        float4 hv0 = h4[0], hv1 = h4[1], hv2 = h4[2], hv3 = h4[3];

        float ar0 = 0.f, az0 = 0.f, an0 = 0.f;
        float ar1 = 0.f, az1 = 0.f, an1 = 0.f;
        ar0 = fmaf(wr[0].x, hv0.x, ar0); az0 = fmaf(wz[0].x, hv0.x, az0); an0 = fmaf(wn[0].x, hv0.x, an0);
        ar0 = fmaf(wr[0].y, hv0.y, ar0); az0 = fmaf(wz[0].y, hv0.y, az0); an0 = fmaf(wn[0].y, hv0.y, an0);
        ar0 = fmaf(wr[0].z, hv0.z, ar0); az0 = fmaf(wz[0].z, hv0.z, az0); an0 = fmaf(wn[0].z, hv0.z, an0);
        ar0 = fmaf(wr[0].w, hv0.w, ar0); az0 = fmaf(wz[0].w, hv0.w, az0); an0 = fmaf(wn[0].w, hv0.w, an0);
        ar1 = fmaf(wr[1].x, hv1.x, ar1); az1 = fmaf(wz[1].x, hv1.x, az1); an1 = fmaf(wn[1].x, hv1.x, an1);
        ar1 = fmaf(wr[1].y, hv1.y, ar1); az1 = fmaf(wz[1].y, hv1.y, az1); an1 = fmaf(wn[1].y, hv1.y, an1);
        ar1 = fmaf(wr[1].z, hv1.z, ar1); az1 = fmaf(wz[1].z, hv1.z, az1); an1 = fmaf(wn[1].z, hv1.z, an1);
        ar1 = fmaf(wr[1].w, hv1.w, ar1); az1 = fmaf(wz[1].w, hv1.w, az1); an1 = fmaf(wn[1].w, hv1.w, an1);
        ar0 = fmaf(wr[2].x, hv2.x, ar0); az0 = fmaf(wz[2].x, hv2.x, az0); an0 = fmaf(wn[2].x, hv2.x, an0);
        ar0 = fmaf(wr[2].y, hv2.y, ar0); az0 = fmaf(wz[2].y, hv2.y, az0); an0 = fmaf(wn[2].y, hv2.y, an0);
        ar0 = fmaf(wr[2].z, hv2.z, ar0); az0 = fmaf(wz[2].z, hv2.z, az0); an0 = fmaf(wn[2].z, hv2.z, an0);
        ar0 = fmaf(wr[2].w, hv2.w, ar0); az0 = fmaf(wz[2].w, hv2.w, az0); an0 = fmaf(wn[2].w, hv2.w, an0);
        ar1 = fmaf(wr[3].x, hv3.x, ar1); az1 = fmaf(wz[3].x, hv3.x, az1); an1 = fmaf(wn[3].x, hv3.x, an1);
        ar1 = fmaf(wr[3].y, hv3.y, ar1); az1 = fmaf(wz[3].y, hv3.y, az1); an1 = fmaf(wn[3].y, hv3.y, an1);
        ar1 = fmaf(wr[3].z, hv3.z, ar1); az1 = fmaf(wz[3].z, hv3.z, az1); an1 = fmaf(wn[3].z, hv3.z, an1);
        ar1 = fmaf(wr[3].w, hv3.w, ar1); az1 = fmaf(wz[3].w, hv3.w, az1); an1 = fmaf(wn[3].w, hv3.w, an1);
        float ar = ar0 + ar1, az = az0 + az1, an = an0 + an1;

        ar += __shfl_xor_sync(0xffffffffu, ar, 1);
        az += __shfl_xor_sync(0xffffffffu, az, 1);
        an += __shfl_xor_sync(0xffffffffu, an, 1);
        ar += __shfl_xor_sync(0xffffffffu, ar, 2);
        az += __shfl_xor_sync(0xffffffffu, az, 2);
        an += __shfl_xor_sync(0xffffffffu, an, 2);
        ar += bhr; az += bhz; an += bhn;

        float r = sigm(xr + ar);
        float z = sigm(xz + az);
        float n = tanh_fast(xn + r * ar);
        float hold = hc[j];
        float hnew = (1.f - z) * n + z * hold;
        if (q == 0) hx[j] = hnew;
        __syncthreads();
        float* tmp = hc; hc = hx; hx = tmp;
    }

    if (tid < O_) {
        float acc = bout[tid];
        #pragma unroll
        for (int k = 0; k < 64; k++) acc = fmaf(hc[k], Wout[tid * 64 + k], acc);
        out[b * O_ + tid] = acc;
    }
}

// ---------------------------------------------------------------------------
// Launch
// ---------------------------------------------------------------------------
extern "C" void kernel_launch(void* const* d_in, const int* in_sizes, int n_in,
                              void* d_out, int out_size)
{
    const float* x    = (const float*)d_in[0];
    const float* ve   = (const float*)d_in[1];
    const float* Wir  = (const float*)d_in[2];
    const float* Wiz  = (const float*)d_in[3];
    const float* Win  = (const float*)d_in[4];
    const float* Whr  = (const float*)d_in[5];
    const float* Whz  = (const float*)d_in[6];
    const float* Whn  = (const float*)d_in[7];
    const float* bir  = (const float*)d_in[8];
    const float* biz  = (const float*)d_in[9];
    const float* bin  = (const float*)d_in[10];
    const float* bhr  = (const float*)d_in[11];
    const float* bhz  = (const float*)d_in[12];
    const float* bhn  = (const float*)d_in[13];
    const float* Wout = (const float*)d_in[14];
    const float* bout = (const float*)d_in[15];
    (void)in_sizes; (void)n_in; (void)out_size;

    cudaFuncSetAttribute(k_gru, cudaFuncAttributeMaxDynamicSharedMemorySize,
                         GRU_SMEM);

    k_wsplit<<<NTILES, 256>>>(ve);
    k_embed_gemm<<<dim3(16, KSPLIT), 256>>>(x);
    k_reduce<<<512, 256>>>();
    k_proj<<<dim3(32, 3), 256>>>(Wir, Wiz, Win, bir, biz, bin);
    k_gru<<<32, 256, GRU_SMEM>>>(Whr, Whz, Whn, bhr, bhz, bhn, Wout, bout,
                                 (float*)d_out);
}

// round 16
// speedup vs baseline: 3.8716x; 1.0501x over previous
#include <cuda_runtime.h>
#include <cuda_fp16.h>
#include <math.h>
#include <stdint.h>

// Problem constants
#define B_      32
#define T_      64
#define V_      30000
#define E_      64
#define H_      64
#define O_      7
#define M_      2048
#define KSPLIT  18
#define KCHUNK  1728            // 27 * 64
#define BK      64
#define NTILES  486             // KSPLIT * 27 (covers ceil(30000/64)=469, rest zero)

// ---------------------------------------------------------------------------
// Scratch (device globals; no allocations allowed)
// ---------------------------------------------------------------------------
__device__ float g_partial[KSPLIT * M_ * E_];   // [s][row][n]
__device__ float g_rowsum[KSPLIT * M_];
__device__ float g_proj[3 * M_ * E_];
// Pre-swizzled fp16 W tiles: [tile][512 x uint4] = 8KB per 64k x 64n tile
__device__ uint4 g_whi[NTILES * 512];

// ---------------------------------------------------------------------------
// MMA helpers (warp-level HMMA fp16, fp32 accum)
// ---------------------------------------------------------------------------
__device__ __forceinline__ void ldsm_x4(uint32_t* r, uint32_t addr) {
    asm volatile("ldmatrix.sync.aligned.m8n8.x4.shared.b16 {%0,%1,%2,%3}, [%4];"
        : "=r"(r[0]), "=r"(r[1]), "=r"(r[2]), "=r"(r[3]) : "r"(addr));
}
__device__ __forceinline__ void ldsm_x4_t(uint32_t* r, uint32_t addr) {
    asm volatile("ldmatrix.sync.aligned.m8n8.x4.trans.shared.b16 {%0,%1,%2,%3}, [%4];"
        : "=r"(r[0]), "=r"(r[1]), "=r"(r[2]), "=r"(r[3]) : "r"(addr));
}
__device__ __forceinline__ void mma_f16(float* d, const uint32_t* a,
                                        uint32_t b0, uint32_t b1) {
    asm volatile("mma.sync.aligned.m16n8k16.row.col.f32.f16.f16.f32 "
        "{%0,%1,%2,%3}, {%4,%5,%6,%7}, {%8,%9}, {%0,%1,%2,%3};"
        : "+f"(d[0]), "+f"(d[1]), "+f"(d[2]), "+f"(d[3])
        : "r"(a[0]), "r"(a[1]), "r"(a[2]), "r"(a[3]), "r"(b0), "r"(b1));
}
// pack two fp32 -> fp16x2 word, low half = first arg
__device__ __forceinline__ uint32_t pack_f16(float lo, float hi) {
    uint32_t w;
    asm("cvt.rn.f16x2.f32 %0, %1, %2;" : "=r"(w) : "f"(hi), "f"(lo));
    return w;
}
__device__ __forceinline__ void cp_async16(uint32_t smem_dst, const void* gsrc) {
    asm volatile("cp.async.cg.shared.global [%0], [%1], 16;"
        :: "r"(smem_dst), "l"(gsrc) : "memory");
}

// ---------------------------------------------------------------------------
// Kernel 0: W prep. W (V x 64 fp32) -> fp16 tiles, SW128-swizzled,
//   ldsm-ready 8KB per 64k x 64n tile. One block per tile.
// ---------------------------------------------------------------------------
__global__ void __launch_bounds__(256) k_wsplit(const float* __restrict__ w)
{
    const int t   = blockIdx.x;
    const int tid = threadIdx.x;
    const int np  = tid & 31;      // n-pair index (cols 2np, 2np+1)
    const int rq  = tid >> 5;      // 0..7

    char* hib_base = (char*)g_whi + (size_t)t * 8192;

    #pragma unroll
    for (int i = 0; i < 8; i++) {
        int kr = i * 8 + rq;                 // 0..63
        int kg = t * 64 + kr;
        float2 v = make_float2(0.f, 0.f);
        if (kg < V_) v = *(const float2*)(w + (size_t)kg * 64 + 2 * np);
        __half h0 = __float2half_rn(v.x), h1 = __float2half_rn(v.y);
        uint32_t hib = (uint32_t)__half_as_ushort(h0) |
                       ((uint32_t)__half_as_ushort(h1) << 16);
        uint32_t off = (uint32_t)(kr * 128 + np * 4);
        uint32_t sw  = off ^ ((kr & 7) << 4);
        *(uint32_t*)(hib_base + sw) = hib;
    }
}

// ---------------------------------------------------------------------------
// Kernel 1: split-K embed GEMM (HMMA fp16, single product).
//   x fp16 (in-kernel convert); W fp16 pre-swizzled via cp.async
//   (double-buffered). fp32 rowsum from x registers (fma pipe, overlaps MMA).
//   CTA: M=128 x N=64, BK=64; 8 warps, each m16 x n64. Grid 16x18 = 1 wave.
// ---------------------------------------------------------------------------
__global__ void __launch_bounds__(256, 2) k_embed_gemm(const float* __restrict__ x)
{
    __shared__ __align__(128) unsigned char sA[16384];     // 128r x 64k fp16
    __shared__ __align__(128) unsigned char sB[2][8192];   // W tile per buffer

    const uint32_t aBase  = (uint32_t)__cvta_generic_to_shared(sA);
    const uint32_t bBase0 = (uint32_t)__cvta_generic_to_shared(sB[0]);
    const uint32_t bBase1 = (uint32_t)__cvta_generic_to_shared(sB[1]);

    const int tid = threadIdx.x;
    const int wr  = tid >> 5;          // warp id -> rows wr*16..+16
    const int l   = tid & 31;
    const int rt  = blockIdx.x;        // 16 row tiles
    const int s   = blockIdx.y;        // 18 k splits
    const int row0  = rt * 128;
    const int tile0 = s * 27;

    // x-load mapping: row = tid>>1, 8 float4 groups starting at (tid&1)*8
    const int xrow = tid >> 1;
    const int xcg  = (tid & 1) * 8;

    // ldmatrix lane geometry
    const int ml = l >> 3;
    const int a_sub  = (ml & 1) * 8 + (l & 7);
    const int a_coff = (ml >> 1) * 16;
    const int b_krow_sub = ((l >> 3) & 1) * 8 + (l & 7);
    const int b_noff     = ((l >> 4) & 1) * 16;

    float d[8][4];
    #pragma unroll
    for (int g = 0; g < 8; g++)
        #pragma unroll
        for (int i = 0; i < 4; i++) d[g][i] = 0.f;
    float rsum = 0.f;

    // ---- prologue: W(0) via cp.async; x(0) into registers ----
    {
        const uint4* src_h = g_whi + (size_t)tile0 * 512;
        #pragma unroll
        for (int j = 0; j < 2; j++) {
            int idx = tid + 256 * j;
            cp_async16(bBase0 + idx * 16, src_h + idx);
        }
        asm volatile("cp.async.commit_group;" ::: "memory");
    }
    float4 xv[8];
    {
        const float* xp = x + (size_t)(row0 + xrow) * V_ + tile0 * 64;
        #pragma unroll
        for (int i = 0; i < 8; i++) {
            int c = 4 * (xcg + i);
            xv[i] = (tile0 * 64 + c < V_) ? __ldcs((const float4*)(xp + c))
                                          : make_float4(0.f, 0.f, 0.f, 0.f);
        }
    }

    for (int it = 0; it < 27; it++) {
        const uint32_t bCur = (it & 1) ? bBase1 : bBase0;

        __syncthreads();   // prior iteration's mma done -> sA free

        // ---- store x tile as fp16 (A: [m][k] 128B rows, SW128) + fp32 rowsum --
        #pragma unroll
        for (int i = 0; i < 8; i++) {
            uint32_t off = (uint32_t)(xrow * 128 + 8 * (xcg + i));
            uint32_t sw  = off ^ ((xrow & 7) << 4);
            uint32_t w0 = pack_f16(xv[i].x, xv[i].y);
            uint32_t w1 = pack_f16(xv[i].z, xv[i].w);
            *(uint2*)(sA + sw) = make_uint2(w0, w1);
            rsum += (xv[i].x + xv[i].y) + (xv[i].z + xv[i].w);
        }

        // ---- prefetch W(it+1) into other buffer ----
        if (it < 26) {
            const uint32_t bNext = (it & 1) ? bBase0 : bBase1;
            const uint4* src_h = g_whi + (size_t)(tile0 + it + 1) * 512;
            #pragma unroll
            for (int j = 0; j < 2; j++) {
                int idx = tid + 256 * j;
                cp_async16(bNext + idx * 16, src_h + idx);
            }
            asm volatile("cp.async.commit_group;" ::: "memory");
            asm volatile("cp.async.wait_group 1;" ::: "memory");  // W(it) arrived
        } else {
            asm volatile("cp.async.wait_group 0;" ::: "memory");
        }
        __syncthreads();   // A + W(it) visible to all warps

        // ---- prefetch x(it+1) into regs (hidden behind mma below) ----
        if (it < 26) {
            int kb = (tile0 + it + 1) * 64;
            const float* xp = x + (size_t)(row0 + xrow) * V_ + kb;
            #pragma unroll
            for (int i = 0; i < 8; i++) {
                int c = 4 * (xcg + i);
                xv[i] = (kb + c < V_) ? __ldcs((const float4*)(xp + c))
                                      : make_float4(0.f, 0.f, 0.f, 0.f);
            }
        }

        // ---- mma: 4 k16 steps x 4 n16 regions (single product) ----
        #pragma unroll
        for (int kk = 0; kk < 4; kk++) {
            uint32_t a[4];
            {
                int row = wr * 16 + a_sub;
                uint32_t off = (uint32_t)(row * 128 + kk * 32 + a_coff);
                ldsm_x4(a, aBase + (off ^ ((row & 7) << 4)));
            }
            #pragma unroll
            for (int nr = 0; nr < 4; nr++) {
                int krow = kk * 16 + b_krow_sub;
                uint32_t off = (uint32_t)(krow * 128 + nr * 32 + b_noff);
                uint32_t sw  = off ^ ((krow & 7) << 4);
                uint32_t bh[4];
                ldsm_x4_t(bh, bCur + sw);
                mma_f16(d[nr * 2 + 0], a, bh[0], bh[1]);
                mma_f16(d[nr * 2 + 1], a, bh[2], bh[3]);
            }
        }
    }

    // ---- epilogue: write partial tile ----
    {
        int r0 = row0 + wr * 16 + (l >> 2);
        #pragma unroll
        for (int g = 0; g < 8; g++) {
            int col = g * 8 + (l & 3) * 2;
            size_t base = ((size_t)s * M_ + r0) * 64 + col;
            *(float2*)(g_partial + base)       = make_float2(d[g][0], d[g][1]);
            *(float2*)(g_partial + base + 512) = make_float2(d[g][2], d[g][3]);
        }
    }
    // ---- rowsum: thread pair (even,odd) covered one row ----
    rsum += __shfl_xor_sync(0xffffffffu, rsum, 1);
    if ((tid & 1) == 0)
        g_rowsum[s * M_ + row0 + xrow] = rsum;
}

// ---------------------------------------------------------------------------
// Kernel 2: fused reduce + input projections.
//   Block = 64 embed rows. Phase 1: reduce 18 split partials + rowsum ->
//   embed tile in smem (g_embed eliminated). Phase 2: all 3 projections.
// ---------------------------------------------------------------------------
__global__ void __launch_bounds__(256) k_reduce_proj(const float* __restrict__ Wir,
                                                     const float* __restrict__ Wiz,
                                                     const float* __restrict__ Win,
                                                     const float* __restrict__ bir,
                                                     const float* __restrict__ biz,
                                                     const float* __restrict__ bin)
{
    __shared__ float es[64 * 65];   // embed rows, padded
    __shared__ float inv_rs[64];
    __shared__ float wt[64 * 64];   // wt[e*64 + j] = W[j][e] (per-mat reuse)

    const int tid = threadIdx.x;
    const int r0  = blockIdx.x * 64;

    // rowsum reciprocal
    if (tid < 64) {
        float rs = 0.f;
        #pragma unroll
        for (int s = 0; s < KSPLIT; s++) rs += g_rowsum[s * M_ + r0 + tid];
        inv_rs[tid] = rs;   // keep sum; divide below for exact match semantics
    }
    __syncthreads();

    // reduce partials -> embed (relu(acc / rs))
    #pragma unroll
    for (int i = 0; i < 4; i++) {
        int idx = tid + i * 256;          // 1024 float4 slots
        int row = idx >> 4;
        int c4  = idx & 15;
        float4 acc = make_float4(0.f, 0.f, 0.f, 0.f);
        #pragma unroll
        for (int s = 0; s < KSPLIT; s++) {
            float4 v = *(const float4*)(g_partial +
                        ((size_t)s * M_ + r0 + row) * 64 + 4 * c4);
            acc.x += v.x; acc.y += v.y; acc.z += v.z; acc.w += v.w;
        }
        float rs = inv_rs[row];
        es[row * 65 + 4 * c4 + 0] = fmaxf(acc.x / rs, 0.f);
        es[row * 65 + 4 * c4 + 1] = fmaxf(acc.y / rs, 0.f);
        es[row * 65 + 4 * c4 + 2] = fmaxf(acc.z / rs, 0.f);
        es[row * 65 + 4 * c4 + 3] = fmaxf(acc.w / rs, 0.f);
    }

    const int tx = tid & 15, ty = tid >> 4;

    #pragma unroll
    for (int mat = 0; mat < 3; mat++) {
        const float* W  = (mat == 0) ? Wir : (mat == 1) ? Wiz : Win;
        const float* bb = (mat == 0) ? bir : (mat == 1) ? biz : bin;

        __syncthreads();   // es ready (mat 0) / wt free (mat >0)
        #pragma unroll
        for (int i = 0; i < 16; i++) {
            int flat = tid + i * 256;
            int r = flat >> 6, c = flat & 63;
            wt[c * 64 + r] = W[flat];
        }
        __syncthreads();

        float accf[4][4] = {};
        #pragma unroll
        for (int e = 0; e < 64; e++) {
            float a0 = es[(4 * ty + 0) * 65 + e];
            float a1 = es[(4 * ty + 1) * 65 + e];
            float a2 = es[(4 * ty + 2) * 65 + e];
            float a3 = es[(4 * ty + 3) * 65 + e];
            float w0 = wt[e * 64 + 4 * tx + 0];
            float w1 = wt[e * 64 + 4 * tx + 1];
            float w2 = wt[e * 64 + 4 * tx + 2];
            float w3 = wt[e * 64 + 4 * tx + 3];
            accf[0][0] = fmaf(a0, w0, accf[0][0]); accf[0][1] = fmaf(a0, w1, accf[0][1]);
            accf[0][2] = fmaf(a0, w2, accf[0][2]); accf[0][3] = fmaf(a0, w3, accf[0][3]);
            accf[1][0] = fmaf(a1, w0, accf[1][0]); accf[1][1] = fmaf(a1, w1, accf[1][1]);
            accf[1][2] = fmaf(a1, w2, accf[1][2]); accf[1][3] = fmaf(a1, w3, accf[1][3]);
            accf[2][0] = fmaf(a2, w0, accf[2][0]); accf[2][1] = fmaf(a2, w1, accf[2][1]);
            accf[2][2] = fmaf(a2, w2, accf[2][2]); accf[2][3] = fmaf(a2, w3, accf[2][3]);
            accf[3][0] = fmaf(a3, w0, accf[3][0]); accf[3][1] = fmaf(a3, w1, accf[3][1]);
            accf[3][2] = fmaf(a3, w2, accf[3][2]); accf[3][3] = fmaf(a3, w3, accf[3][3]);
        }
        float b0 = bb[4 * tx + 0], b1 = bb[4 * tx + 1];
        float b2 = bb[4 * tx + 2], b3 = bb[4 * tx + 3];
        #pragma unroll
        for (int i = 0; i < 4; i++) {
            int row = r0 + 4 * ty + i;
            float* o = g_proj + (size_t)mat * (M_ * 64) + row * 64 + 4 * tx;
            o[0] = accf[i][0] + b0;
            o[1] = accf[i][1] + b1;
            o[2] = accf[i][2] + b2;
            o[3] = accf[i][3] + b3;
        }
    }
}

// ---------------------------------------------------------------------------
// Kernel 3: per-batch GRU scan + head (proj staged in smem, weights in regs)
// ---------------------------------------------------------------------------
#define GRU_SMEM ((3 * 4096 + 128) * 4)

__device__ __forceinline__ float sigm(float v) {
    return __fdividef(1.f, 1.f + __expf(-v));
}
__device__ __forceinline__ float tanh_fast(float v) {
    float e = __expf(2.f * v);
    return __fdividef(e - 1.f, e + 1.f);
}

__global__ void __launch_bounds__(256) k_gru(const float* __restrict__ Whr,
                                             const float* __restrict__ Whz,
                                             const float* __restrict__ Whn,
                                             const float* __restrict__ bhr_g,
                                             const float* __restrict__ bhz_g,
                                             const float* __restrict__ bhn_g,
                                             const float* __restrict__ Wout,
                                             const float* __restrict__ bout,
                                             float* __restrict__ out)
{
    extern __shared__ float sp[];
    float* sr = sp;
    float* sz = sp + 4096;
    float* sn = sp + 8192;
    float* ha = sp + 12288;
    float* hb = ha + 64;

    const int tid = threadIdx.x;
    const int j   = tid >> 2;
    const int q   = tid & 3;
    const int b   = blockIdx.x;

    #pragma unroll
    for (int m = 0; m < 3; m++) {
        const float4* src = (const float4*)(g_proj + (size_t)m * (M_ * 64) + b * 4096);
        float4* dst = (float4*)(sp + m * 4096);
        #pragma unroll
        for (int i = 0; i < 4; i++) {
            int idx = tid + i * 256;
            dst[idx] = src[idx];
        }
    }

    float4 wr[4], wz[4], wn[4];
    {
        const float4* r4 = (const float4*)(Whr + j * 64 + q * 16);
        const float4* z4 = (const float4*)(Whz + j * 64 + q * 16);
        const float4* n4 = (const float4*)(Whn + j * 64 + q * 16);
        #pragma unroll
        for (int u = 0; u < 4; u++) { wr[u] = r4[u]; wz[u] = z4[u]; wn[u] = n4[u]; }
    }
    const float bhr = bhr_g[j], bhz = bhz_g[j], bhn = bhn_g[j];
    __syncthreads();

    {
        float z1 = sigm(sz[j]);
        float n1 = tanh_fast(sn[j]);
        if (q == 0) ha[j] = (1.f - z1) * n1;
    }
    __syncthreads();

    float* hc = ha;
    float* hx = hb;
    for (int t = 1; t < T_; t++) {
        float xr = sr[t * 64 + j];
        float xz = sz[t * 64 + j];
        float xn = sn[t * 64 + j];

        const float4* h4 = (const float4*)(hc + q * 16);
        float4 hv0 = h4[0], hv1 = h4[1], hv2 = h4[2], hv3 = h4[3];

        float ar0 = 0.f, az0 = 0.f, an0 = 0.f;
        float ar1 = 0.f, az1 = 0.f, an1 = 0.f;
        ar0 = fmaf(wr[0].x, hv0.x, ar0); az0 = fmaf(wz[0].x, hv0.x, az0); an0 = fmaf(wn[0].x, hv0.x, an0);
        ar0 = fmaf(wr[0].y, hv0.y, ar0); az0 = fmaf(wz[0].y, hv0.y, az0); an0 = fmaf(wn[0].y, hv0.y, an0);
        ar0 = fmaf(wr[0].z, hv0.z, ar0); az0 = fmaf(wz[0].z, hv0.z, az0); an0 = fmaf(wn[0].z, hv0.z, an0);
        ar0 = fmaf(wr[0].w, hv0.w, ar0); az0 = fmaf(wz[0].w, hv0.w, az0); an0 = fmaf(wn[0].w, hv0.w, an0);
        ar1 = fmaf(wr[1].x, hv1.x, ar1); az1 = fmaf(wz[1].x, hv1.x, az1); an1 = fmaf(wn[1].x, hv1.x, an1);
        ar1 = fmaf(wr[1].y, hv1.y, ar1); az1 = fmaf(wz[1].y, hv1.y, az1); an1 = fmaf(wn[1].y, hv1.y, an1);
        ar1 = fmaf(wr[1].z, hv1.z, ar1); az1 = fmaf(wz[1].z, hv1.z, az1); an1 = fmaf(wn[1].z, hv1.z, an1);
        ar1 = fmaf(wr[1].w, hv1.w, ar1); az1 = fmaf(wz[1].w, hv1.w, az1); an1 = fmaf(wn[1].w, hv1.w, an1);
        ar0 = fmaf(wr[2].x, hv2.x, ar0); az0 = fmaf(wz[2].x, hv2.x, az0); an0 = fmaf(wn[2].x, hv2.x, an0);
        ar0 = fmaf(wr[2].y, hv2.y, ar0); az0 = fmaf(wz[2].y, hv2.y, az0); an0 = fmaf(wn[2].y, hv2.y, an0);
        ar0 = fmaf(wr[2].z, hv2.z, ar0); az0 = fmaf(wz[2].z, hv2.z, az0); an0 = fmaf(wn[2].z, hv2.z, an0);
        ar0 = fmaf(wr[2].w, hv2.w, ar0); az0 = fmaf(wz[2].w, hv2.w, az0); an0 = fmaf(wn[2].w, hv2.w, an0);
        ar1 = fmaf(wr[3].x, hv3.x, ar1); az1 = fmaf(wz[3].x, hv3.x, az1); an1 = fmaf(wn[3].x, hv3.x, an1);
        ar1 = fmaf(wr[3].y, hv3.y, ar1); az1 = fmaf(wz[3].y, hv3.y, az1); an1 = fmaf(wn[3].y, hv3.y, an1);
        ar1 = fmaf(wr[3].z, hv3.z, ar1); az1 = fmaf(wz[3].z, hv3.z, az1); an1 = fmaf(wn[3].z, hv3.z, an1);
        ar1 = fmaf(wr[3].w, hv3.w, ar1); az1 = fmaf(wz[3].w, hv3.w, az1); an1 = fmaf(wn[3].w, hv3.w, an1);
        float ar = ar0 + ar1, az = az0 + az1, an = an0 + an1;

        ar += __shfl_xor_sync(0xffffffffu, ar, 1);
        az += __shfl_xor_sync(0xffffffffu, az, 1);
        an += __shfl_xor_sync(0xffffffffu, an, 1);
        ar += __shfl_xor_sync(0xffffffffu, ar, 2);
        az += __shfl_xor_sync(0xffffffffu, az, 2);
        an += __shfl_xor_sync(0xffffffffu, an, 2);
        ar += bhr; az += bhz; an += bhn;

        float r = sigm(xr + ar);
        float z = sigm(xz + az);
        float n = tanh_fast(xn + r * ar);
        float hold = hc[j];
        float hnew = (1.f - z) * n + z * hold;
        if (q == 0) hx[j] = hnew;
        __syncthreads();
        float* tmp = hc; hc = hx; hx = tmp;
    }

    if (tid < O_) {
        float acc = bout[tid];
        #pragma unroll
        for (int k = 0; k < 64; k++) acc = fmaf(hc[k], Wout[tid * 64 + k], acc);
        out[b * O_ + tid] = acc;
    }
}

// ---------------------------------------------------------------------------
// Launch
// ---------------------------------------------------------------------------
extern "C" void kernel_launch(void* const* d_in, const int* in_sizes, int n_in,
                              void* d_out, int out_size)
{
    const float* x    = (const float*)d_in[0];
    const float* ve   = (const float*)d_in[1];
    const float* Wir  = (const float*)d_in[2];
    const float* Wiz  = (const float*)d_in[3];
    const float* Win  = (const float*)d_in[4];
    const float* Whr  = (const float*)d_in[5];
    const float* Whz  = (const float*)d_in[6];
    const float* Whn  = (const float*)d_in[7];
    const float* bir  = (const float*)d_in[8];
    const float* biz  = (const float*)d_in[9];
    const float* bin  = (const float*)d_in[10];
    const float* bhr  = (const float*)d_in[11];
    const float* bhz  = (const float*)d_in[12];
    const float* bhn  = (const float*)d_in[13];
    const float* Wout = (const float*)d_in[14];
    const float* bout = (const float*)d_in[15];
    (void)in_sizes; (void)n_in; (void)out_size;

    cudaFuncSetAttribute(k_gru, cudaFuncAttributeMaxDynamicSharedMemorySize,
                         GRU_SMEM);

    k_wsplit<<<NTILES, 256>>>(ve);
    k_embed_gemm<<<dim3(16, KSPLIT), 256>>>(x);
    k_reduce_proj<<<32, 256>>>(Wir, Wiz, Win, bir, biz, bin);
    k_gru<<<32, 256, GRU_SMEM>>>(Whr, Whz, Whn, bhr, bhz, bhn, Wout, bout,
                                 (float*)d_out);
}